// round 12
// baseline (speedup 1.0000x reference)
#include <cuda_runtime.h>
#include <math.h>
#include <stdint.h>

#define TOK   1024   // B*S
#define SLEN  256
#define BATCH 4
#define HID   512
#define DINP  1024
#define GHID  2048
#define NPRE  4096   // 2 dirs * 4H

#define NBLK     64      // blocks in lstm kernel (each owns both directions)
#define FLAG_PAD 32      // one 128B line per flag

typedef unsigned long long ull;

// ---------------- device scratch (static, no allocation) ----------------
__device__ float g_xA[TOK * DINP];
__device__ float g_xB[TOK * DINP];
__device__ float g_pre[TOK * NPRE];
__device__ float g_pa[TOK * HID];
__device__ float g_pb[TOK * HID];
__device__ float    g_h[2 * 2 * HID * 4];          // [buf][dir][k][batch]
__device__ unsigned g_flag[2 * NBLK * FLAG_PAD];   // [dir][blk] step counters

// ---------------- helpers ----------------
__device__ __forceinline__ float tanh_fast(float x) {
    float y;
    asm("tanh.approx.f32 %0, %1;" : "=f"(y) : "f"(x));
    return y;
}
__device__ __forceinline__ float sig_fast(float x) {
    return 0.5f * tanh_fast(0.5f * x) + 0.5f;
}
__device__ __forceinline__ ull pk2(float x) {
    ull d; asm("mov.b64 %0, {%1, %1};" : "=l"(d) : "f"(x)); return d;
}
__device__ __forceinline__ void fma2(ull& acc, ull a, ull b) {
    asm("fma.rn.f32x2 %0, %1, %2, %0;" : "+l"(acc) : "l"(a), "l"(b));
}
__device__ __forceinline__ void add2(ull& acc, ull a) {
    asm("add.rn.f32x2 %0, %0, %1;" : "+l"(acc) : "l"(a));
}
__device__ __forceinline__ float lo2(ull v) { return __uint_as_float((unsigned)v); }
__device__ __forceinline__ float hi2(ull v) { return __uint_as_float((unsigned)(v >> 32)); }
__device__ __forceinline__ unsigned ld_acq(const unsigned* p) {
    unsigned v;
    asm volatile("ld.acquire.gpu.global.b32 %0, [%1];" : "=r"(v) : "l"(p));
    return v;
}
__device__ __forceinline__ void st_rel(unsigned* p, unsigned v) {
    asm volatile("st.release.gpu.global.b32 [%0], %1;" :: "l"(p), "r"(v));
}
__device__ __forceinline__ void backoff() {
    asm volatile("nanosleep.u32 100;");
}

__global__ void zero_flags_kernel() {
    g_flag[blockIdx.x * 256 + threadIdx.x] = 0u;
}

// ---------------- embedding gather + concat ----------------
__global__ __launch_bounds__(256) void embed_kernel(
    const int* __restrict__ sent, const int* __restrict__ pos,
    const float* __restrict__ emb)
{
    int gid = blockIdx.x * 256 + threadIdx.x;
    int token = gid >> 8;
    int q = gid & 255;
    const float4* src;
    if (q < 128) src = (const float4*)(emb + (size_t)sent[token] * HID) + q;
    else         src = (const float4*)(emb + (size_t)pos[token]  * HID) + (q - 128);
    ((float4*)g_xA)[gid] = *src;
}

// ---------------- fp32x2 SIMT GEMM: C[M,N] = A[M,K] * B[N,K]^T + bias(n) ----------------
__global__ __launch_bounds__(256) void gemm_kernel(
    const float* __restrict__ A, const float* __restrict__ B,
    float* __restrict__ C, int N, int K, int ldb,
    const float* __restrict__ bias1, const float* __restrict__ bias2)
{
    __shared__ float As[16][128];
    __shared__ float Bs[16][128];
    const int tid = threadIdx.x;
    const int bm = blockIdx.y << 7, bn = blockIdx.x << 7;
    const int row = tid >> 1;
    const int kq  = (tid & 1) << 3;
    const int tx = tid & 15, ty = tid >> 4;
    const int n0 = tx << 2, m0 = ty << 2;

    const float* Ap = A + (size_t)(bm + row) * K + kq;
    const float* Bp = B + (size_t)(bn + row) * ldb + kq;

    ull acc[8][4];
#pragma unroll
    for (int i = 0; i < 8; i++)
#pragma unroll
        for (int j = 0; j < 4; j++) acc[i][j] = 0ull;

    float4 a0v = *(const float4*)(Ap);
    float4 a1v = *(const float4*)(Ap + 4);
    float4 b0v = *(const float4*)(Bp);
    float4 b1v = *(const float4*)(Bp + 4);

    for (int k0 = 0; k0 < K; k0 += 16) {
        As[kq + 0][row] = a0v.x; As[kq + 1][row] = a0v.y;
        As[kq + 2][row] = a0v.z; As[kq + 3][row] = a0v.w;
        As[kq + 4][row] = a1v.x; As[kq + 5][row] = a1v.y;
        As[kq + 6][row] = a1v.z; As[kq + 7][row] = a1v.w;
        Bs[kq + 0][row] = b0v.x; Bs[kq + 1][row] = b0v.y;
        Bs[kq + 2][row] = b0v.z; Bs[kq + 3][row] = b0v.w;
        Bs[kq + 4][row] = b1v.x; Bs[kq + 5][row] = b1v.y;
        Bs[kq + 6][row] = b1v.z; Bs[kq + 7][row] = b1v.w;
        __syncthreads();

        if (k0 + 16 < K) {
            a0v = *(const float4*)(Ap + k0 + 16);
            a1v = *(const float4*)(Ap + k0 + 20);
            b0v = *(const float4*)(Bp + k0 + 16);
            b1v = *(const float4*)(Bp + k0 + 20);
        }

#pragma unroll
        for (int k = 0; k < 16; k++) {
            float4 am0 = *(const float4*)&As[k][m0];
            float4 am1 = *(const float4*)&As[k][m0 + 64];
            ulonglong2 bb0 = *(const ulonglong2*)&Bs[k][n0];
            ulonglong2 bb1 = *(const ulonglong2*)&Bs[k][n0 + 64];
            ull ad[8];
            ad[0] = pk2(am0.x); ad[1] = pk2(am0.y); ad[2] = pk2(am0.z); ad[3] = pk2(am0.w);
            ad[4] = pk2(am1.x); ad[5] = pk2(am1.y); ad[6] = pk2(am1.z); ad[7] = pk2(am1.w);
#pragma unroll
            for (int i = 0; i < 8; i++) {
                fma2(acc[i][0], ad[i], bb0.x);
                fma2(acc[i][1], ad[i], bb0.y);
                fma2(acc[i][2], ad[i], bb1.x);
                fma2(acc[i][3], ad[i], bb1.y);
            }
        }
        __syncthreads();
    }

    float bz[8];
#pragma unroll
    for (int jj = 0; jj < 8; jj++) {
        int n = bn + n0 + ((jj < 4) ? jj : 60 + jj);
        float bb = 0.0f;
        if (bias1) bb += bias1[n];
        if (bias2) bb += bias2[n];
        bz[jj] = bb;
    }
#pragma unroll
    for (int i = 0; i < 8; i++) {
        int m = bm + m0 + ((i < 4) ? i : 60 + i);
        float* Cr = C + (size_t)m * N + bn + n0;
        Cr[0]  = lo2(acc[i][0]) + bz[0];
        Cr[1]  = hi2(acc[i][0]) + bz[1];
        Cr[2]  = lo2(acc[i][1]) + bz[2];
        Cr[3]  = hi2(acc[i][1]) + bz[3];
        Cr[64] = lo2(acc[i][2]) + bz[4];
        Cr[65] = hi2(acc[i][2]) + bz[5];
        Cr[66] = lo2(acc[i][3]) + bz[6];
        Cr[67] = hi2(acc[i][3]) + bz[7];
    }
}

// ---------------- persistent bidirectional LSTM scan, direction-interleaved ----------------
// 64 blocks; each owns units [blk*8, blk*8+8) of BOTH directions and alternates
// fwd-phase / bwd-phase each iteration. While one direction computes, the other
// direction's publish->detect latency elapses -> sync latency hidden.
// Per-direction protocol identical to R7-R11 (flags, double buffer, release/acquire).
__global__ __launch_bounds__(256, 1) void lstm_kernel(
    const float* __restrict__ pre,     // [TOK][4096], bias folded
    const float* __restrict__ whh,     // [2][2048][512] this layer
    const int* __restrict__ length,
    float* __restrict__ xout,          // [TOK][1024]
    int base)                          // l*SLEN
{
    __shared__ float4 hbuf[512];       // h[k][4 batch]
    __shared__ ull    red2[512];       // matvec partials (packed batch pairs)
    __shared__ ull    gsum2[64];       // reduced gates  (packed batch pairs)

    const int tid = threadIdx.x;
    const int blk = blockIdx.x;        // 0..63
    const int u0  = blk * 8;
    const int r   = tid & 31;          // local gate-row (gate = r>>3, j = r&7)
    const int kc  = tid >> 5;          // k-chunk 0..7

    // register-resident scalar W_hh slices, both directions
    float wF[64], wB[64];
    {
        const float* wpF = whh + (size_t)((r >> 3) * HID + u0 + (r & 7)) * HID + kc * 64;
        const float* wpB = wpF + (size_t)GHID * HID;
#pragma unroll
        for (int kk = 0; kk < 64; kk++) { wF[kk] = wpF[kk]; wB[kk] = wpB[kk]; }
    }

    const bool is_w7 = (tid >= 224);
    const int lane = tid & 31;
    const int j7 = lane & 7, b7 = lane >> 3;
    float cF = 0.f, hF = 0.f, cB = 0.f, hB = 0.f;
    const int len_b = is_w7 ? length[b7] : 0;

    unsigned* flagF = &g_flag[blk * FLAG_PAD];
    unsigned* flagB = &g_flag[(NBLK + blk) * FLAG_PAD];
    const unsigned* dflagsF = &g_flag[0];
    const unsigned* dflagsB = &g_flag[NBLK * FLAG_PAD];

#define PHASE(D, WREG, CREG, HREG, MYFLAG, DFLAGS)                                   \
    {                                                                                 \
        const int t = (D) ? (SLEN - 1 - s) : s;                                       \
        float pi = 0.f, pf = 0.f, pg = 0.f, po = 0.f;                                 \
        if (is_w7) {                                                                  \
            const float* pp = pre + (size_t)(b7 * SLEN + t) * NPRE + (D) * GHID + u0 + j7; \
            pi = pp[0]; pf = pp[512]; pg = pp[1024]; po = pp[1536];                   \
        }                                                                             \
        if (s == 0) {                                                                 \
            hbuf[2 * tid]     = make_float4(0.f, 0.f, 0.f, 0.f);                      \
            hbuf[2 * tid + 1] = make_float4(0.f, 0.f, 0.f, 0.f);                      \
        } else {                                                                      \
            const unsigned want = (unsigned)(base + s);                               \
            const unsigned* fl = (DFLAGS) + (tid >> 2) * FLAG_PAD;                    \
            if (ld_acq(fl) < want) {                                                  \
                do { backoff(); } while (ld_acq(fl) < want);                          \
            }                                                                         \
            const float4* src = ((const float4*)g_h) + ((s & 1) * 2 + (D)) * 512 + 2 * tid; \
            hbuf[2 * tid]     = __ldcg(src);                                          \
            hbuf[2 * tid + 1] = __ldcg(src + 1);                                      \
        }                                                                             \
        __syncthreads();                                                              \
        ull a01 = 0ull, a23 = 0ull;                                                   \
        const ulonglong2* hp = (const ulonglong2*)(hbuf + kc * 64);                   \
        _Pragma("unroll")                                                             \
        for (int kk = 0; kk < 64; kk++) {                                             \
            ulonglong2 hv = hp[kk];                                                   \
            ull wd = pk2((WREG)[kk]);                                                 \
            fma2(a01, wd, hv.x);                                                      \
            fma2(a23, wd, hv.y);                                                      \
        }                                                                             \
        red2[tid] = a01;                                                              \
        red2[256 + tid] = a23;                                                        \
        __syncthreads();                                                              \
        if (tid < 64) {                                                               \
            const int rr = tid & 31, half = tid >> 5;                                 \
            const ull* rp = red2 + half * 256 + rr;                                   \
            ull sum = rp[0];                                                          \
            _Pragma("unroll")                                                         \
            for (int q = 1; q < 8; q++) add2(sum, rp[q * 32]);                        \
            gsum2[half * 32 + rr] = sum;                                              \
        }                                                                             \
        __syncthreads();                                                              \
        if (is_w7) {                                                                  \
            const float* gs = (const float*)gsum2;                                    \
            const int bb = (b7 >> 1) * 64 + (b7 & 1);                                 \
            float gi = pi + gs[bb + (0 * 8 + j7) * 2];                                \
            float gf = pf + gs[bb + (1 * 8 + j7) * 2];                                \
            float gg = pg + gs[bb + (2 * 8 + j7) * 2];                                \
            float go = po + gs[bb + (3 * 8 + j7) * 2];                                \
            float cn = sig_fast(gf) * (CREG) + sig_fast(gi) * tanh_fast(gg);          \
            float hn = sig_fast(go) * tanh_fast(cn);                                  \
            bool m = (t < len_b);                                                     \
            if (m) { (CREG) = cn; (HREG) = hn; }                                      \
            __stcg(&((float*)g_h)[((((s + 1) & 1) * 2 + (D)) * 512 + u0 + j7) * 4 + b7], (HREG)); \
            __syncwarp();                                                             \
            if (lane == 0) st_rel((MYFLAG), (unsigned)(base + s + 1));                \
            xout[(size_t)(b7 * SLEN + t) * DINP + (D) * HID + u0 + j7] = m ? hn : 0.0f; \
        }                                                                             \
    }

    for (int s = 0; s < SLEN; s++) {
        PHASE(0, wF, cF, hF, flagF, dflagsF)
        PHASE(1, wB, cB, hB, flagB, dflagsB)
    }
#undef PHASE
}

// ---------------- score: out[b,s,t] = b2 + sum_h w2[h]*tanh(pa[b,s,h]+pbb[b,t,h]) ----------------
__global__ __launch_bounds__(256) void score_kernel(
    const float* __restrict__ pa, const float* __restrict__ pb,
    const float* __restrict__ w2, const float* __restrict__ b2,
    float* __restrict__ out)
{
    extern __shared__ float sm[];
    float* paT = sm;                 // [512][17]
    float* pbT = sm + 512 * 17;
    float* w2s = pbT + 512 * 17;     // [512]

    const int tid = threadIdx.x;
    const int btt = blockIdx.x, bss = blockIdx.y, b = blockIdx.z;

    for (int idx = tid; idx < 16 * 512; idx += 256) {
        int row = idx >> 9, h = idx & 511;
        paT[h * 17 + row] = pa[(size_t)(b * SLEN + bss * 16 + row) * HID + h];
        pbT[h * 17 + row] = pb[(size_t)(b * SLEN + btt * 16 + row) * HID + h];
    }
    for (int idx = tid; idx < 512; idx += 256) w2s[idx] = w2[idx];
    __syncthreads();

    const int si = tid & 15, ti = tid >> 4;
    float acc = 0.0f;
#pragma unroll 8
    for (int h = 0; h < 512; h++) {
        float x = paT[h * 17 + si] + pbT[h * 17 + ti];
        acc = fmaf(w2s[h], tanh_fast(x), acc);
    }
    out[(size_t)(b * SLEN + bss * 16 + si) * SLEN + btt * 16 + ti] = acc + b2[0];
}

// ---------------- launch ----------------
extern "C" void kernel_launch(void* const* d_in, const int* in_sizes, int n_in,
                              void* d_out, int out_size)
{
    const int*   sent   = (const int*)d_in[0];
    const int*   pos    = (const int*)d_in[1];
    const int*   length = (const int*)d_in[2];
    const float* emb    = (const float*)d_in[3];
    const float* w_ih   = (const float*)d_in[4];
    const float* w_hh   = (const float*)d_in[5];
    const float* b_ih   = (const float*)d_in[6];
    const float* b_hh   = (const float*)d_in[7];
    const float* w1     = (const float*)d_in[8];
    const float* b1     = (const float*)d_in[9];
    const float* w2     = (const float*)d_in[10];
    const float* b2     = (const float*)d_in[11];
    float* out = (float*)d_out;

    const int SCORE_SMEM = 2 * 512 * 17 * 4 + 512 * 4;
    cudaFuncSetAttribute(score_kernel, cudaFuncAttributeMaxDynamicSharedMemorySize, SCORE_SMEM);

    float *xA, *xB, *prep, *pap, *pbp;
    cudaGetSymbolAddress((void**)&xA,   g_xA);
    cudaGetSymbolAddress((void**)&xB,   g_xB);
    cudaGetSymbolAddress((void**)&prep, g_pre);
    cudaGetSymbolAddress((void**)&pap,  g_pa);
    cudaGetSymbolAddress((void**)&pbp,  g_pb);

    zero_flags_kernel<<<(2 * NBLK * FLAG_PAD) / 256, 256>>>();
    embed_kernel<<<1024, 256>>>(sent, pos, emb);

    for (int l = 0; l < 2; l++) {
        const float* Ain = l ? xB : xA;
        float* Xout      = l ? xA : xB;
        gemm_kernel<<<dim3(NPRE / 128, TOK / 128), 256>>>(
            Ain, w_ih + (size_t)l * NPRE * DINP, prep,
            NPRE, DINP, DINP, b_ih + l * NPRE, b_hh + l * NPRE);
        lstm_kernel<<<NBLK, 256>>>(
            prep, w_hh + (size_t)l * 2 * GHID * HID, length, Xout, l * SLEN);
    }

    gemm_kernel<<<dim3(HID / 128, TOK / 128), 256>>>(
        xA, w1,        pap, HID, DINP, 2048, nullptr, nullptr);
    gemm_kernel<<<dim3(HID / 128, TOK / 128), 256>>>(
        xA, w1 + 1024, pbp, HID, DINP, 2048, b1, nullptr);

    score_kernel<<<dim3(16, 16, 4), 256, SCORE_SMEM>>>(pap, pbp, w2, b2, out);
}

// round 13
// speedup vs baseline: 1.4154x; 1.4154x over previous
#include <cuda_runtime.h>
#include <math.h>
#include <stdint.h>

#define TOK   1024   // B*S
#define SLEN  256
#define BATCH 4
#define HID   512
#define DINP  1024
#define GHID  2048
#define NPRE  4096   // 2 dirs * 4H

#define NBLK     64      // blocks per direction in lstm kernel
#define NBLK_TOT 128
#define FLAG_PAD 32      // one 128B line per flag

typedef unsigned long long ull;

// ---------------- device scratch (static, no allocation) ----------------
__device__ float g_xA[TOK * DINP];
__device__ float g_xB[TOK * DINP];
__device__ float g_pre[TOK * NPRE];
__device__ float g_pa[TOK * HID];
__device__ float g_pb[TOK * HID];
__device__ float    g_h[2 * 2 * HID * 4];          // [buf][dir][k][batch]
__device__ unsigned g_flag[NBLK_TOT * FLAG_PAD];   // per-block step counters

// ---------------- helpers ----------------
__device__ __forceinline__ float tanh_fast(float x) {
    float y;
    asm("tanh.approx.f32 %0, %1;" : "=f"(y) : "f"(x));
    return y;
}
__device__ __forceinline__ float sig_fast(float x) {
    return 0.5f * tanh_fast(0.5f * x) + 0.5f;
}
__device__ __forceinline__ ull pk2(float x) {
    ull d; asm("mov.b64 %0, {%1, %1};" : "=l"(d) : "f"(x)); return d;
}
__device__ __forceinline__ void fma2(ull& acc, ull a, ull b) {
    asm("fma.rn.f32x2 %0, %1, %2, %0;" : "+l"(acc) : "l"(a), "l"(b));
}
__device__ __forceinline__ void add2(ull& acc, ull a) {
    asm("add.rn.f32x2 %0, %0, %1;" : "+l"(acc) : "l"(a));
}
__device__ __forceinline__ float lo2(ull v) { return __uint_as_float((unsigned)v); }
__device__ __forceinline__ float hi2(ull v) { return __uint_as_float((unsigned)(v >> 32)); }
__device__ __forceinline__ unsigned ld_acq(const unsigned* p) {
    unsigned v;
    asm volatile("ld.acquire.gpu.global.b32 %0, [%1];" : "=r"(v) : "l"(p));
    return v;
}
__device__ __forceinline__ void st_rel(unsigned* p, unsigned v) {
    asm volatile("st.release.gpu.global.b32 [%0], %1;" :: "l"(p), "r"(v));
}
__device__ __forceinline__ void backoff() {
    asm volatile("nanosleep.u32 100;");
}

__global__ void zero_flags_kernel() {
    g_flag[blockIdx.x * 256 + threadIdx.x] = 0u;
}

// ---------------- embedding gather + concat ----------------
__global__ __launch_bounds__(256) void embed_kernel(
    const int* __restrict__ sent, const int* __restrict__ pos,
    const float* __restrict__ emb)
{
    int gid = blockIdx.x * 256 + threadIdx.x;
    int token = gid >> 8;
    int q = gid & 255;
    const float4* src;
    if (q < 128) src = (const float4*)(emb + (size_t)sent[token] * HID) + q;
    else         src = (const float4*)(emb + (size_t)pos[token]  * HID) + (q - 128);
    ((float4*)g_xA)[gid] = *src;
}

// ---------------- fp32x2 SIMT GEMM: C[M,N] = A[M,K] * B[N,K]^T + bias(n) ----------------
__global__ __launch_bounds__(256) void gemm_kernel(
    const float* __restrict__ A, const float* __restrict__ B,
    float* __restrict__ C, int N, int K, int ldb,
    const float* __restrict__ bias1, const float* __restrict__ bias2)
{
    __shared__ float As[16][128];
    __shared__ float Bs[16][128];
    const int tid = threadIdx.x;
    const int bm = blockIdx.y << 7, bn = blockIdx.x << 7;
    const int row = tid >> 1;
    const int kq  = (tid & 1) << 3;
    const int tx = tid & 15, ty = tid >> 4;
    const int n0 = tx << 2, m0 = ty << 2;

    const float* Ap = A + (size_t)(bm + row) * K + kq;
    const float* Bp = B + (size_t)(bn + row) * ldb + kq;

    ull acc[8][4];
#pragma unroll
    for (int i = 0; i < 8; i++)
#pragma unroll
        for (int j = 0; j < 4; j++) acc[i][j] = 0ull;

    float4 a0v = *(const float4*)(Ap);
    float4 a1v = *(const float4*)(Ap + 4);
    float4 b0v = *(const float4*)(Bp);
    float4 b1v = *(const float4*)(Bp + 4);

    for (int k0 = 0; k0 < K; k0 += 16) {
        As[kq + 0][row] = a0v.x; As[kq + 1][row] = a0v.y;
        As[kq + 2][row] = a0v.z; As[kq + 3][row] = a0v.w;
        As[kq + 4][row] = a1v.x; As[kq + 5][row] = a1v.y;
        As[kq + 6][row] = a1v.z; As[kq + 7][row] = a1v.w;
        Bs[kq + 0][row] = b0v.x; Bs[kq + 1][row] = b0v.y;
        Bs[kq + 2][row] = b0v.z; Bs[kq + 3][row] = b0v.w;
        Bs[kq + 4][row] = b1v.x; Bs[kq + 5][row] = b1v.y;
        Bs[kq + 6][row] = b1v.z; Bs[kq + 7][row] = b1v.w;
        __syncthreads();

        if (k0 + 16 < K) {
            a0v = *(const float4*)(Ap + k0 + 16);
            a1v = *(const float4*)(Ap + k0 + 20);
            b0v = *(const float4*)(Bp + k0 + 16);
            b1v = *(const float4*)(Bp + k0 + 20);
        }

#pragma unroll
        for (int k = 0; k < 16; k++) {
            float4 am0 = *(const float4*)&As[k][m0];
            float4 am1 = *(const float4*)&As[k][m0 + 64];
            ulonglong2 bb0 = *(const ulonglong2*)&Bs[k][n0];
            ulonglong2 bb1 = *(const ulonglong2*)&Bs[k][n0 + 64];
            ull ad[8];
            ad[0] = pk2(am0.x); ad[1] = pk2(am0.y); ad[2] = pk2(am0.z); ad[3] = pk2(am0.w);
            ad[4] = pk2(am1.x); ad[5] = pk2(am1.y); ad[6] = pk2(am1.z); ad[7] = pk2(am1.w);
#pragma unroll
            for (int i = 0; i < 8; i++) {
                fma2(acc[i][0], ad[i], bb0.x);
                fma2(acc[i][1], ad[i], bb0.y);
                fma2(acc[i][2], ad[i], bb1.x);
                fma2(acc[i][3], ad[i], bb1.y);
            }
        }
        __syncthreads();
    }

    float bz[8];
#pragma unroll
    for (int jj = 0; jj < 8; jj++) {
        int n = bn + n0 + ((jj < 4) ? jj : 60 + jj);
        float bb = 0.0f;
        if (bias1) bb += bias1[n];
        if (bias2) bb += bias2[n];
        bz[jj] = bb;
    }
#pragma unroll
    for (int i = 0; i < 8; i++) {
        int m = bm + m0 + ((i < 4) ? i : 60 + i);
        float* Cr = C + (size_t)m * N + bn + n0;
        Cr[0]  = lo2(acc[i][0]) + bz[0];
        Cr[1]  = hi2(acc[i][0]) + bz[1];
        Cr[2]  = lo2(acc[i][1]) + bz[2];
        Cr[3]  = hi2(acc[i][1]) + bz[3];
        Cr[64] = lo2(acc[i][2]) + bz[4];
        Cr[65] = hi2(acc[i][2]) + bz[5];
        Cr[66] = lo2(acc[i][3]) + bz[6];
        Cr[67] = hi2(acc[i][3]) + bz[7];
    }
}

// ---------------- persistent bidirectional LSTM scan (R11 base, warp-local S1) ----------------
// 128 blocks: [0,64) fwd, [64,128) bwd; each owns 8 hidden units (32 gate rows).
// KEY: warp w polls exactly producers [8w,8w+8) and writes exactly hbuf chunk
// [64w,64w+64) — the chunk ONLY warp kc=w reads in its matvec. So the gather
// barrier is warp-local (__syncwarp), decoupling straggler waits per warp.
// red2 WAR(s+1 write vs s read) protected by S3; gsum2 WAR by S2.
__global__ __launch_bounds__(256, 1) void lstm_kernel(
    const float* __restrict__ pre,     // [TOK][4096], bias folded
    const float* __restrict__ whh,     // [2][2048][512] this layer
    const int* __restrict__ length,
    float* __restrict__ xout,          // [TOK][1024]
    int base)                          // l*SLEN
{
    __shared__ float4 hbuf[512];       // h[k][4 batch]
    __shared__ ull    red2[512];       // matvec partials (packed batch pairs)
    __shared__ ull    gsum2[64];       // reduced gates  (packed batch pairs)

    const int tid = threadIdx.x;
    const int d   = blockIdx.x >> 6;
    const int blk = blockIdx.x & 63;
    const int u0  = blk * 8;
    const int r   = tid & 31;          // local gate-row (gate = r>>3, j = r&7)
    const int kc  = tid >> 5;          // k-chunk 0..7 (= warp id)

    // register-resident scalar W_hh slice
    float wreg[64];
    {
        const float* wp = whh + (size_t)d * GHID * HID
                        + (size_t)((r >> 3) * HID + u0 + (r & 7)) * HID + kc * 64;
#pragma unroll
        for (int kk = 0; kk < 64; kk++) wreg[kk] = wp[kk];
    }

    const bool is_w7 = (tid >= 224);
    const int lane = tid & 31;
    const int j7 = lane & 7, b7 = lane >> 3;
    float creg = 0.0f, hreg = 0.0f;
    const int len_b = is_w7 ? length[b7] : 0;

    unsigned* myflag = &g_flag[blockIdx.x * FLAG_PAD];
    const unsigned* dirflags = &g_flag[(d * NBLK) * FLAG_PAD];

    for (int s = 0; s < SLEN; s++) {
        const int t = d ? (SLEN - 1 - s) : s;

        // warp7: prefetch pre-activations for owned gates (independent of h)
        float pi = 0.f, pf = 0.f, pg = 0.f, po = 0.f;
        if (is_w7) {
            const float* pp = pre + (size_t)(b7 * SLEN + t) * NPRE + d * GHID + u0 + j7;
            pi = pp[0]; pf = pp[512]; pg = pp[1024]; po = pp[1536];
        }

        // warp-local poll+gather: warp w handles producers [8w,8w+8) = its own chunk
        if (s == 0) {
            hbuf[2 * tid]     = make_float4(0.f, 0.f, 0.f, 0.f);
            hbuf[2 * tid + 1] = make_float4(0.f, 0.f, 0.f, 0.f);
        } else {
            const unsigned want = (unsigned)(base + s);
            const unsigned* fl = dirflags + (tid >> 2) * FLAG_PAD;
            // first check free; then backoff-poll to avoid LTS queue storm
            if (ld_acq(fl) < want) {
                do { backoff(); } while (ld_acq(fl) < want);
            }
            const float4* src = ((const float4*)g_h) + ((s & 1) * 2 + d) * 512 + 2 * tid;
            hbuf[2 * tid]     = __ldcg(src);
            hbuf[2 * tid + 1] = __ldcg(src + 1);
        }
        __syncwarp();      // warp-local: this warp's chunk of hbuf is ready

        // matvec: thread (r, kc), 64 k per thread, batch-packed f32x2
        ull a01 = 0ull, a23 = 0ull;
        const ulonglong2* hp = (const ulonglong2*)(hbuf + kc * 64);
#pragma unroll
        for (int kk = 0; kk < 64; kk++) {
            ulonglong2 hv = hp[kk];          // LDS.128 broadcast within warp
            ull wd = pk2(wreg[kk]);          // ALU mov, dual-issues vs fma pipe
            fma2(a01, wd, hv.x);
            fma2(a23, wd, hv.y);
        }
        red2[tid] = a01;
        red2[256 + tid] = a23;
        __syncthreads();   // S2: all partials in red2

        // packed 8-way reduction: 64 threads
        if (tid < 64) {
            const int rr = tid & 31, half = tid >> 5;
            const ull* rp = red2 + half * 256 + rr;
            ull sum = rp[0];
#pragma unroll
            for (int q = 1; q < 8; q++) add2(sum, rp[q * 32]);
            gsum2[half * 32 + rr] = sum;
        }
        __syncthreads();   // S3: gate sums ready; also fences red2 reads vs next write

        // warp7: activation + publish (runs while other warps start next poll)
        if (is_w7) {
            const float* gs = (const float*)gsum2;
            const int bb = (b7 >> 1) * 64 + (b7 & 1);
            float gi = pi + gs[bb + (0 * 8 + j7) * 2];
            float gf = pf + gs[bb + (1 * 8 + j7) * 2];
            float gg = pg + gs[bb + (2 * 8 + j7) * 2];
            float go = po + gs[bb + (3 * 8 + j7) * 2];
            float cn = sig_fast(gf) * creg + sig_fast(gi) * tanh_fast(gg);
            float hn = sig_fast(go) * tanh_fast(cn);
            bool m = (t < len_b);
            if (m) { creg = cn; hreg = hn; }
            // publish h (buffer (s+1)&1): 32 consecutive floats = one 128B line
            __stcg(&((float*)g_h)[((((s + 1) & 1) * 2 + d) * 512 + u0 + j7) * 4 + b7], hreg);
            __syncwarp();                     // warp-scope memory order: h-line HB release
            if (lane == 0) st_rel(myflag, (unsigned)(base + s + 1));
            // xout after release: off the critical path
            xout[(size_t)(b7 * SLEN + t) * DINP + d * HID + u0 + j7] = m ? hn : 0.0f;
        }
    }
}

// ---------------- score: out[b,s,t] = b2 + sum_h w2[h]*tanh(pa[b,s,h]+pbb[b,t,h]) ----------------
__global__ __launch_bounds__(256) void score_kernel(
    const float* __restrict__ pa, const float* __restrict__ pb,
    const float* __restrict__ w2, const float* __restrict__ b2,
    float* __restrict__ out)
{
    extern __shared__ float sm[];
    float* paT = sm;                 // [512][17]
    float* pbT = sm + 512 * 17;
    float* w2s = pbT + 512 * 17;     // [512]

    const int tid = threadIdx.x;
    const int btt = blockIdx.x, bss = blockIdx.y, b = blockIdx.z;

    for (int idx = tid; idx < 16 * 512; idx += 256) {
        int row = idx >> 9, h = idx & 511;
        paT[h * 17 + row] = pa[(size_t)(b * SLEN + bss * 16 + row) * HID + h];
        pbT[h * 17 + row] = pb[(size_t)(b * SLEN + btt * 16 + row) * HID + h];
    }
    for (int idx = tid; idx < 512; idx += 256) w2s[idx] = w2[idx];
    __syncthreads();

    const int si = tid & 15, ti = tid >> 4;
    float acc = 0.0f;
#pragma unroll 8
    for (int h = 0; h < 512; h++) {
        float x = paT[h * 17 + si] + pbT[h * 17 + ti];
        acc = fmaf(w2s[h], tanh_fast(x), acc);
    }
    out[(size_t)(b * SLEN + bss * 16 + si) * SLEN + btt * 16 + ti] = acc + b2[0];
}

// ---------------- launch ----------------
extern "C" void kernel_launch(void* const* d_in, const int* in_sizes, int n_in,
                              void* d_out, int out_size)
{
    const int*   sent   = (const int*)d_in[0];
    const int*   pos    = (const int*)d_in[1];
    const int*   length = (const int*)d_in[2];
    const float* emb    = (const float*)d_in[3];
    const float* w_ih   = (const float*)d_in[4];
    const float* w_hh   = (const float*)d_in[5];
    const float* b_ih   = (const float*)d_in[6];
    const float* b_hh   = (const float*)d_in[7];
    const float* w1     = (const float*)d_in[8];
    const float* b1     = (const float*)d_in[9];
    const float* w2     = (const float*)d_in[10];
    const float* b2     = (const float*)d_in[11];
    float* out = (float*)d_out;

    const int SCORE_SMEM = 2 * 512 * 17 * 4 + 512 * 4;
    cudaFuncSetAttribute(score_kernel, cudaFuncAttributeMaxDynamicSharedMemorySize, SCORE_SMEM);

    float *xA, *xB, *prep, *pap, *pbp;
    cudaGetSymbolAddress((void**)&xA,   g_xA);
    cudaGetSymbolAddress((void**)&xB,   g_xB);
    cudaGetSymbolAddress((void**)&prep, g_pre);
    cudaGetSymbolAddress((void**)&pap,  g_pa);
    cudaGetSymbolAddress((void**)&pbp,  g_pb);

    zero_flags_kernel<<<NBLK_TOT * FLAG_PAD / 256, 256>>>();
    embed_kernel<<<1024, 256>>>(sent, pos, emb);

    for (int l = 0; l < 2; l++) {
        const float* Ain = l ? xB : xA;
        float* Xout      = l ? xA : xB;
        gemm_kernel<<<dim3(NPRE / 128, TOK / 128), 256>>>(
            Ain, w_ih + (size_t)l * NPRE * DINP, prep,
            NPRE, DINP, DINP, b_ih + l * NPRE, b_hh + l * NPRE);
        lstm_kernel<<<NBLK_TOT, 256>>>(
            prep, w_hh + (size_t)l * 2 * GHID * HID, length, Xout, l * SLEN);
    }

    gemm_kernel<<<dim3(HID / 128, TOK / 128), 256>>>(
        xA, w1,        pap, HID, DINP, 2048, nullptr, nullptr);
    gemm_kernel<<<dim3(HID / 128, TOK / 128), 256>>>(
        xA, w1 + 1024, pbp, HID, DINP, 2048, b1, nullptr);

    score_kernel<<<dim3(16, 16, 4), 256, SCORE_SMEM>>>(pap, pbp, w2, b2, out);
}

// round 14
// speedup vs baseline: 1.8075x; 1.2770x over previous
#include <cuda_runtime.h>
#include <math.h>
#include <stdint.h>

#define TOK   1024   // B*S
#define SLEN  256
#define BATCH 4
#define HID   512
#define DINP  1024
#define GHID  2048
#define NPRE  4096   // 2 dirs * 4H

#define NBLK     64      // blocks per direction in lstm kernel
#define NBLK_TOT 128

typedef unsigned long long ull;

// ---------------- device scratch (static, no allocation) ----------------
__device__ float g_xA[TOK * DINP];
__device__ float g_xB[TOK * DINP];
__device__ float g_pre[TOK * NPRE];
__device__ float g_pa[TOK * HID];
__device__ float g_pb[TOK * HID];
__device__ float g_h[2 * 2 * HID * 4];   // [buf][dir][k][batch], zero-init at load

// ---------------- helpers ----------------
__device__ __forceinline__ float tanh_fast(float x) {
    float y;
    asm("tanh.approx.f32 %0, %1;" : "=f"(y) : "f"(x));
    return y;
}
__device__ __forceinline__ float sig_fast(float x) {
    return 0.5f * tanh_fast(0.5f * x) + 0.5f;
}
__device__ __forceinline__ ull pk2(float x) {
    ull d; asm("mov.b64 %0, {%1, %1};" : "=l"(d) : "f"(x)); return d;
}
__device__ __forceinline__ void fma2(ull& acc, ull a, ull b) {
    asm("fma.rn.f32x2 %0, %1, %2, %0;" : "+l"(acc) : "l"(a), "l"(b));
}
__device__ __forceinline__ void add2(ull& acc, ull a) {
    asm("add.rn.f32x2 %0, %0, %1;" : "+l"(acc) : "l"(a));
}
__device__ __forceinline__ float lo2(ull v) { return __uint_as_float((unsigned)v); }
__device__ __forceinline__ float hi2(ull v) { return __uint_as_float((unsigned)(v >> 32)); }
__device__ __forceinline__ uint4 ldcg4(const uint4* p) {
    uint4 v;
    asm volatile("ld.global.cg.v4.u32 {%0,%1,%2,%3}, [%4];"
        : "=r"(v.x), "=r"(v.y), "=r"(v.z), "=r"(v.w) : "l"(p) : "memory");
    return v;
}
__device__ __forceinline__ void stcg1u(float* p, unsigned v) {
    asm volatile("st.global.cg.b32 [%0], %1;" :: "l"(p), "r"(v) : "memory");
}
__device__ __forceinline__ void backoff() {
    asm volatile("nanosleep.u32 64;");
}

// ---------------- embedding gather + concat ----------------
__global__ __launch_bounds__(256) void embed_kernel(
    const int* __restrict__ sent, const int* __restrict__ pos,
    const float* __restrict__ emb)
{
    int gid = blockIdx.x * 256 + threadIdx.x;
    int token = gid >> 8;
    int q = gid & 255;
    const float4* src;
    if (q < 128) src = (const float4*)(emb + (size_t)sent[token] * HID) + q;
    else         src = (const float4*)(emb + (size_t)pos[token]  * HID) + (q - 128);
    ((float4*)g_xA)[gid] = *src;
}

// ---------------- fp32x2 SIMT GEMM: C[M,N] = A[M,K] * B[N,K]^T + bias(n) ----------------
__global__ __launch_bounds__(256) void gemm_kernel(
    const float* __restrict__ A, const float* __restrict__ B,
    float* __restrict__ C, int N, int K, int ldb,
    const float* __restrict__ bias1, const float* __restrict__ bias2)
{
    __shared__ float As[16][128];
    __shared__ float Bs[16][128];
    const int tid = threadIdx.x;
    const int bm = blockIdx.y << 7, bn = blockIdx.x << 7;
    const int row = tid >> 1;
    const int kq  = (tid & 1) << 3;
    const int tx = tid & 15, ty = tid >> 4;
    const int n0 = tx << 2, m0 = ty << 2;

    const float* Ap = A + (size_t)(bm + row) * K + kq;
    const float* Bp = B + (size_t)(bn + row) * ldb + kq;

    ull acc[8][4];
#pragma unroll
    for (int i = 0; i < 8; i++)
#pragma unroll
        for (int j = 0; j < 4; j++) acc[i][j] = 0ull;

    float4 a0v = *(const float4*)(Ap);
    float4 a1v = *(const float4*)(Ap + 4);
    float4 b0v = *(const float4*)(Bp);
    float4 b1v = *(const float4*)(Bp + 4);

    for (int k0 = 0; k0 < K; k0 += 16) {
        As[kq + 0][row] = a0v.x; As[kq + 1][row] = a0v.y;
        As[kq + 2][row] = a0v.z; As[kq + 3][row] = a0v.w;
        As[kq + 4][row] = a1v.x; As[kq + 5][row] = a1v.y;
        As[kq + 6][row] = a1v.z; As[kq + 7][row] = a1v.w;
        Bs[kq + 0][row] = b0v.x; Bs[kq + 1][row] = b0v.y;
        Bs[kq + 2][row] = b0v.z; Bs[kq + 3][row] = b0v.w;
        Bs[kq + 4][row] = b1v.x; Bs[kq + 5][row] = b1v.y;
        Bs[kq + 6][row] = b1v.z; Bs[kq + 7][row] = b1v.w;
        __syncthreads();

        if (k0 + 16 < K) {
            a0v = *(const float4*)(Ap + k0 + 16);
            a1v = *(const float4*)(Ap + k0 + 20);
            b0v = *(const float4*)(Bp + k0 + 16);
            b1v = *(const float4*)(Bp + k0 + 20);
        }

#pragma unroll
        for (int k = 0; k < 16; k++) {
            float4 am0 = *(const float4*)&As[k][m0];
            float4 am1 = *(const float4*)&As[k][m0 + 64];
            ulonglong2 bb0 = *(const ulonglong2*)&Bs[k][n0];
            ulonglong2 bb1 = *(const ulonglong2*)&Bs[k][n0 + 64];
            ull ad[8];
            ad[0] = pk2(am0.x); ad[1] = pk2(am0.y); ad[2] = pk2(am0.z); ad[3] = pk2(am0.w);
            ad[4] = pk2(am1.x); ad[5] = pk2(am1.y); ad[6] = pk2(am1.z); ad[7] = pk2(am1.w);
#pragma unroll
            for (int i = 0; i < 8; i++) {
                fma2(acc[i][0], ad[i], bb0.x);
                fma2(acc[i][1], ad[i], bb0.y);
                fma2(acc[i][2], ad[i], bb1.x);
                fma2(acc[i][3], ad[i], bb1.y);
            }
        }
        __syncthreads();
    }

    float bz[8];
#pragma unroll
    for (int jj = 0; jj < 8; jj++) {
        int n = bn + n0 + ((jj < 4) ? jj : 60 + jj);
        float bb = 0.0f;
        if (bias1) bb += bias1[n];
        if (bias2) bb += bias2[n];
        bz[jj] = bb;
    }
#pragma unroll
    for (int i = 0; i < 8; i++) {
        int m = bm + m0 + ((i < 4) ? i : 60 + i);
        float* Cr = C + (size_t)m * N + bn + n0;
        Cr[0]  = lo2(acc[i][0]) + bz[0];
        Cr[1]  = hi2(acc[i][0]) + bz[1];
        Cr[2]  = lo2(acc[i][1]) + bz[2];
        Cr[3]  = hi2(acc[i][1]) + bz[3];
        Cr[64] = lo2(acc[i][2]) + bz[4];
        Cr[65] = hi2(acc[i][2]) + bz[5];
        Cr[66] = lo2(acc[i][3]) + bz[6];
        Cr[67] = hi2(acc[i][3]) + bz[7];
    }
}

// ---------------- persistent bidirectional LSTM scan (R13 + parity-tagged h) ----------------
// 128 blocks: [0,64) fwd, [64,128) bwd; each owns 8 hidden units (32 gate rows).
// Sync: 2-bit step tag embedded in the low mantissa bits of every published h
// word. Publish at step s carries tag (base+s+1)&3; gather at step s polls its
// own 8 words (weak ld.cg) until ALL carry tag (base+s)&3. Data IS the flag:
// one L2 round trip, no fences/atomics/acquire/release. Tag perturbation is
// <= 3 ulp (~3.6e-7 rel). Gather barrier is warp-local (__syncwarp, R13).
__global__ __launch_bounds__(256, 1) void lstm_kernel(
    const float* __restrict__ pre,     // [TOK][4096], bias folded
    const float* __restrict__ whh,     // [2][2048][512] this layer
    const int* __restrict__ length,
    float* __restrict__ xout,          // [TOK][1024]
    int base)                          // l*SLEN
{
    __shared__ float4 hbuf[512];       // h[k][4 batch]
    __shared__ ull    red2[512];       // matvec partials (packed batch pairs)
    __shared__ ull    gsum2[64];       // reduced gates  (packed batch pairs)

    const int tid = threadIdx.x;
    const int d   = blockIdx.x >> 6;
    const int blk = blockIdx.x & 63;
    const int u0  = blk * 8;
    const int r   = tid & 31;          // local gate-row (gate = r>>3, j = r&7)
    const int kc  = tid >> 5;          // k-chunk 0..7 (= warp id)

    // register-resident scalar W_hh slice
    float wreg[64];
    {
        const float* wp = whh + (size_t)d * GHID * HID
                        + (size_t)((r >> 3) * HID + u0 + (r & 7)) * HID + kc * 64;
#pragma unroll
        for (int kk = 0; kk < 64; kk++) wreg[kk] = wp[kk];
    }

    const bool is_w7 = (tid >= 224);
    const int lane = tid & 31;
    const int j7 = lane & 7, b7 = lane >> 3;
    float creg = 0.0f, hreg = 0.0f;
    const int len_b = is_w7 ? length[b7] : 0;

    for (int s = 0; s < SLEN; s++) {
        const int t = d ? (SLEN - 1 - s) : s;

        // warp7: prefetch pre-activations for owned gates (independent of h)
        float pi = 0.f, pf = 0.f, pg = 0.f, po = 0.f;
        if (is_w7) {
            const float* pp = pre + (size_t)(b7 * SLEN + t) * NPRE + d * GHID + u0 + j7;
            pi = pp[0]; pf = pp[512]; pg = pp[1024]; po = pp[1536];
        }

        // warp-local poll+gather: thread tid polls/reads producer (tid>>2)'s words.
        // Tag match on all 8 words == producer finished step s-1. Data is the flag.
        if (s == 0) {
            hbuf[2 * tid]     = make_float4(0.f, 0.f, 0.f, 0.f);
            hbuf[2 * tid + 1] = make_float4(0.f, 0.f, 0.f, 0.f);
        } else {
            const unsigned want = (unsigned)(base + s) & 3u;
            const uint4* src = ((const uint4*)g_h) + ((s & 1) * 2 + d) * 512 + 2 * tid;
            uint4 v0 = ldcg4(src);
            uint4 v1 = ldcg4(src + 1);
            while ((((v0.x ^ want) | (v0.y ^ want) | (v0.z ^ want) | (v0.w ^ want) |
                     (v1.x ^ want) | (v1.y ^ want) | (v1.z ^ want) | (v1.w ^ want)) & 3u) != 0u) {
                backoff();
                v0 = ldcg4(src);
                v1 = ldcg4(src + 1);
            }
            ((uint4*)hbuf)[2 * tid]     = v0;
            ((uint4*)hbuf)[2 * tid + 1] = v1;
        }
        __syncwarp();      // warp-local: this warp's chunk of hbuf is ready

        // matvec: thread (r, kc), 64 k per thread, batch-packed f32x2
        ull a01 = 0ull, a23 = 0ull;
        const ulonglong2* hp = (const ulonglong2*)(hbuf + kc * 64);
#pragma unroll
        for (int kk = 0; kk < 64; kk++) {
            ulonglong2 hv = hp[kk];          // LDS.128 broadcast within warp
            ull wd = pk2(wreg[kk]);          // ALU mov, dual-issues vs fma pipe
            fma2(a01, wd, hv.x);
            fma2(a23, wd, hv.y);
        }
        red2[tid] = a01;
        red2[256 + tid] = a23;
        __syncthreads();   // S2: all partials in red2

        // packed 8-way reduction: 64 threads
        if (tid < 64) {
            const int rr = tid & 31, half = tid >> 5;
            const ull* rp = red2 + half * 256 + rr;
            ull sum = rp[0];
#pragma unroll
            for (int q = 1; q < 8; q++) add2(sum, rp[q * 32]);
            gsum2[half * 32 + rr] = sum;
        }
        __syncthreads();   // S3: gate sums ready; also fences red2 reads vs next write

        // warp7: activation + tagged publish (no fence/release — data is the flag)
        if (is_w7) {
            const float* gs = (const float*)gsum2;
            const int bb = (b7 >> 1) * 64 + (b7 & 1);
            float gi = pi + gs[bb + (0 * 8 + j7) * 2];
            float gf = pf + gs[bb + (1 * 8 + j7) * 2];
            float gg = pg + gs[bb + (2 * 8 + j7) * 2];
            float go = po + gs[bb + (3 * 8 + j7) * 2];
            float cn = sig_fast(gf) * creg + sig_fast(gi) * tanh_fast(gg);
            float hn = sig_fast(go) * tanh_fast(cn);
            bool m = (t < len_b);
            if (m) { creg = cn; hreg = hn; }
            // publish h into buffer (s+1)&1 with 2-bit step tag in low mantissa bits
            const unsigned tag = (unsigned)(base + s + 1) & 3u;
            unsigned hb = (__float_as_uint(hreg) & ~3u) | tag;
            stcg1u(&g_h[((((s + 1) & 1) * 2 + d) * 512 + u0 + j7) * 4 + b7], hb);
            xout[(size_t)(b7 * SLEN + t) * DINP + d * HID + u0 + j7] = m ? hn : 0.0f;
        }
    }
}

// ---------------- score: out[b,s,t] = b2 + sum_h w2[h]*tanh(pa[b,s,h]+pbb[b,t,h]) ----------------
__global__ __launch_bounds__(256) void score_kernel(
    const float* __restrict__ pa, const float* __restrict__ pb,
    const float* __restrict__ w2, const float* __restrict__ b2,
    float* __restrict__ out)
{
    extern __shared__ float sm[];
    float* paT = sm;                 // [512][17]
    float* pbT = sm + 512 * 17;
    float* w2s = pbT + 512 * 17;     // [512]

    const int tid = threadIdx.x;
    const int btt = blockIdx.x, bss = blockIdx.y, b = blockIdx.z;

    for (int idx = tid; idx < 16 * 512; idx += 256) {
        int row = idx >> 9, h = idx & 511;
        paT[h * 17 + row] = pa[(size_t)(b * SLEN + bss * 16 + row) * HID + h];
        pbT[h * 17 + row] = pb[(size_t)(b * SLEN + btt * 16 + row) * HID + h];
    }
    for (int idx = tid; idx < 512; idx += 256) w2s[idx] = w2[idx];
    __syncthreads();

    const int si = tid & 15, ti = tid >> 4;
    float acc = 0.0f;
#pragma unroll 8
    for (int h = 0; h < 512; h++) {
        float x = paT[h * 17 + si] + pbT[h * 17 + ti];
        acc = fmaf(w2s[h], tanh_fast(x), acc);
    }
    out[(size_t)(b * SLEN + bss * 16 + si) * SLEN + btt * 16 + ti] = acc + b2[0];
}

// ---------------- launch ----------------
extern "C" void kernel_launch(void* const* d_in, const int* in_sizes, int n_in,
                              void* d_out, int out_size)
{
    const int*   sent   = (const int*)d_in[0];
    const int*   pos    = (const int*)d_in[1];
    const int*   length = (const int*)d_in[2];
    const float* emb    = (const float*)d_in[3];
    const float* w_ih   = (const float*)d_in[4];
    const float* w_hh   = (const float*)d_in[5];
    const float* b_ih   = (const float*)d_in[6];
    const float* b_hh   = (const float*)d_in[7];
    const float* w1     = (const float*)d_in[8];
    const float* b1     = (const float*)d_in[9];
    const float* w2     = (const float*)d_in[10];
    const float* b2     = (const float*)d_in[11];
    float* out = (float*)d_out;

    const int SCORE_SMEM = 2 * 512 * 17 * 4 + 512 * 4;
    cudaFuncSetAttribute(score_kernel, cudaFuncAttributeMaxDynamicSharedMemorySize, SCORE_SMEM);

    float *xA, *xB, *prep, *pap, *pbp;
    cudaGetSymbolAddress((void**)&xA,   g_xA);
    cudaGetSymbolAddress((void**)&xB,   g_xB);
    cudaGetSymbolAddress((void**)&prep, g_pre);
    cudaGetSymbolAddress((void**)&pap,  g_pa);
    cudaGetSymbolAddress((void**)&pbp,  g_pb);

    embed_kernel<<<1024, 256>>>(sent, pos, emb);

    for (int l = 0; l < 2; l++) {
        const float* Ain = l ? xB : xA;
        float* Xout      = l ? xA : xB;
        gemm_kernel<<<dim3(NPRE / 128, TOK / 128), 256>>>(
            Ain, w_ih + (size_t)l * NPRE * DINP, prep,
            NPRE, DINP, DINP, b_ih + l * NPRE, b_hh + l * NPRE);
        lstm_kernel<<<NBLK_TOT, 256>>>(
            prep, w_hh + (size_t)l * 2 * GHID * HID, length, Xout, l * SLEN);
    }

    gemm_kernel<<<dim3(HID / 128, TOK / 128), 256>>>(
        xA, w1,        pap, HID, DINP, 2048, nullptr, nullptr);
    gemm_kernel<<<dim3(HID / 128, TOK / 128), 256>>>(
        xA, w1 + 1024, pbp, HID, DINP, 2048, b1, nullptr);

    score_kernel<<<dim3(16, 16, 4), 256, SCORE_SMEM>>>(pap, pbp, w2, b2, out);
}

// round 15
// speedup vs baseline: 2.0864x; 1.1543x over previous
#include <cuda_runtime.h>
#include <math.h>
#include <stdint.h>

#define TOK   1024   // B*S
#define SLEN  256
#define BATCH 4
#define HID   512
#define DINP  1024
#define GHID  2048
#define NPRE  4096   // 2 dirs * 4H

#define NBLK     64      // blocks per direction in lstm kernel
#define NBLK_TOT 128

typedef unsigned long long ull;

// ---------------- device scratch (static, no allocation) ----------------
__device__ float g_xA[TOK * DINP];
__device__ float g_xB[TOK * DINP];
__device__ float g_pre[TOK * NPRE];
__device__ float g_pa[TOK * HID];
__device__ float g_pb[TOK * HID];
__device__ float g_h[2 * 2 * HID * 4];   // [buf][dir][k][batch], zero-init at load

// ---------------- helpers ----------------
__device__ __forceinline__ float tanh_fast(float x) {
    float y;
    asm("tanh.approx.f32 %0, %1;" : "=f"(y) : "f"(x));
    return y;
}
__device__ __forceinline__ float sig_fast(float x) {
    return 0.5f * tanh_fast(0.5f * x) + 0.5f;
}
__device__ __forceinline__ ull pk2(float x) {
    ull d; asm("mov.b64 %0, {%1, %1};" : "=l"(d) : "f"(x)); return d;
}
__device__ __forceinline__ void fma2(ull& acc, ull a, ull b) {
    asm("fma.rn.f32x2 %0, %1, %2, %0;" : "+l"(acc) : "l"(a), "l"(b));
}
__device__ __forceinline__ void add2(ull& acc, ull a) {
    asm("add.rn.f32x2 %0, %0, %1;" : "+l"(acc) : "l"(a));
}
__device__ __forceinline__ float lo2(ull v) { return __uint_as_float((unsigned)v); }
__device__ __forceinline__ float hi2(ull v) { return __uint_as_float((unsigned)(v >> 32)); }
__device__ __forceinline__ uint4 ldcg4(const uint4* p) {
    uint4 v;
    asm volatile("ld.global.cg.v4.u32 {%0,%1,%2,%3}, [%4];"
        : "=r"(v.x), "=r"(v.y), "=r"(v.z), "=r"(v.w) : "l"(p) : "memory");
    return v;
}
__device__ __forceinline__ void stcg1u(float* p, unsigned v) {
    asm volatile("st.global.cg.b32 [%0], %1;" :: "l"(p), "r"(v) : "memory");
}
__device__ __forceinline__ void backoff() {
    asm volatile("nanosleep.u32 64;");
}

// ---------------- embedding gather + concat ----------------
__global__ __launch_bounds__(256) void embed_kernel(
    const int* __restrict__ sent, const int* __restrict__ pos,
    const float* __restrict__ emb)
{
    int gid = blockIdx.x * 256 + threadIdx.x;
    int token = gid >> 8;
    int q = gid & 255;
    const float4* src;
    if (q < 128) src = (const float4*)(emb + (size_t)sent[token] * HID) + q;
    else         src = (const float4*)(emb + (size_t)pos[token]  * HID) + (q - 128);
    ((float4*)g_xA)[gid] = *src;
}

// ---------------- fp32x2 SIMT GEMM: C[M,N] = A[M,K] * B[N,K]^T + bias(n) ----------------
// __launch_bounds__(256,2): force 2 CTAs/SM so the whole 256-block grid runs
// in one wave (kills the 13.5% wave-quantization tail).
__global__ __launch_bounds__(256, 2) void gemm_kernel(
    const float* __restrict__ A, const float* __restrict__ B,
    float* __restrict__ C, int N, int K, int ldb,
    const float* __restrict__ bias1, const float* __restrict__ bias2)
{
    __shared__ float As[16][128];
    __shared__ float Bs[16][128];
    const int tid = threadIdx.x;
    const int bm = blockIdx.y << 7, bn = blockIdx.x << 7;
    const int row = tid >> 1;
    const int kq  = (tid & 1) << 3;
    const int tx = tid & 15, ty = tid >> 4;
    const int n0 = tx << 2, m0 = ty << 2;

    const float* Ap = A + (size_t)(bm + row) * K + kq;
    const float* Bp = B + (size_t)(bn + row) * ldb + kq;

    ull acc[8][4];
#pragma unroll
    for (int i = 0; i < 8; i++)
#pragma unroll
        for (int j = 0; j < 4; j++) acc[i][j] = 0ull;

    float4 a0v = *(const float4*)(Ap);
    float4 a1v = *(const float4*)(Ap + 4);
    float4 b0v = *(const float4*)(Bp);
    float4 b1v = *(const float4*)(Bp + 4);

    for (int k0 = 0; k0 < K; k0 += 16) {
        As[kq + 0][row] = a0v.x; As[kq + 1][row] = a0v.y;
        As[kq + 2][row] = a0v.z; As[kq + 3][row] = a0v.w;
        As[kq + 4][row] = a1v.x; As[kq + 5][row] = a1v.y;
        As[kq + 6][row] = a1v.z; As[kq + 7][row] = a1v.w;
        Bs[kq + 0][row] = b0v.x; Bs[kq + 1][row] = b0v.y;
        Bs[kq + 2][row] = b0v.z; Bs[kq + 3][row] = b0v.w;
        Bs[kq + 4][row] = b1v.x; Bs[kq + 5][row] = b1v.y;
        Bs[kq + 6][row] = b1v.z; Bs[kq + 7][row] = b1v.w;
        __syncthreads();

        if (k0 + 16 < K) {
            a0v = *(const float4*)(Ap + k0 + 16);
            a1v = *(const float4*)(Ap + k0 + 20);
            b0v = *(const float4*)(Bp + k0 + 16);
            b1v = *(const float4*)(Bp + k0 + 20);
        }

#pragma unroll
        for (int k = 0; k < 16; k++) {
            float4 am0 = *(const float4*)&As[k][m0];
            float4 am1 = *(const float4*)&As[k][m0 + 64];
            ulonglong2 bb0 = *(const ulonglong2*)&Bs[k][n0];
            ulonglong2 bb1 = *(const ulonglong2*)&Bs[k][n0 + 64];
            ull ad[8];
            ad[0] = pk2(am0.x); ad[1] = pk2(am0.y); ad[2] = pk2(am0.z); ad[3] = pk2(am0.w);
            ad[4] = pk2(am1.x); ad[5] = pk2(am1.y); ad[6] = pk2(am1.z); ad[7] = pk2(am1.w);
#pragma unroll
            for (int i = 0; i < 8; i++) {
                fma2(acc[i][0], ad[i], bb0.x);
                fma2(acc[i][1], ad[i], bb0.y);
                fma2(acc[i][2], ad[i], bb1.x);
                fma2(acc[i][3], ad[i], bb1.y);
            }
        }
        __syncthreads();
    }

    float bz[8];
#pragma unroll
    for (int jj = 0; jj < 8; jj++) {
        int n = bn + n0 + ((jj < 4) ? jj : 60 + jj);
        float bb = 0.0f;
        if (bias1) bb += bias1[n];
        if (bias2) bb += bias2[n];
        bz[jj] = bb;
    }
#pragma unroll
    for (int i = 0; i < 8; i++) {
        int m = bm + m0 + ((i < 4) ? i : 60 + i);
        float* Cr = C + (size_t)m * N + bn + n0;
        Cr[0]  = lo2(acc[i][0]) + bz[0];
        Cr[1]  = hi2(acc[i][0]) + bz[1];
        Cr[2]  = lo2(acc[i][1]) + bz[2];
        Cr[3]  = hi2(acc[i][1]) + bz[3];
        Cr[64] = lo2(acc[i][2]) + bz[4];
        Cr[65] = hi2(acc[i][2]) + bz[5];
        Cr[66] = lo2(acc[i][3]) + bz[6];
        Cr[67] = hi2(acc[i][3]) + bz[7];
    }
}

// ---------------- merged attention GEMM: pa = X@wa^T ; pb = X@wb^T + b1 ----------------
// One launch of 64 blocks (vs two sequential 32-block launches).
// Virtual n in [0,1024): n<512 -> pa (wa = w1[:, :1024]); n>=512 -> pb (wb = w1[:, 1024:], +b1).
// 512 % 128 == 0, so each 128-wide n-tile is uniformly pa or pb.
__global__ __launch_bounds__(256, 2) void gemm_attn_kernel(
    const float* __restrict__ A, const float* __restrict__ w1,
    const float* __restrict__ b1)
{
    __shared__ float As[16][128];
    __shared__ float Bs[16][128];
    const int tid = threadIdx.x;
    const int bm = blockIdx.y << 7, bn = blockIdx.x << 7;
    const int row = tid >> 1;
    const int kq  = (tid & 1) << 3;
    const int tx = tid & 15, ty = tid >> 4;
    const int n0 = tx << 2, m0 = ty << 2;

    const bool isB = (bn >= 512);
    const int bnl = isB ? (bn - 512) : bn;           // local n-tile base in [0,512)
    float* Cbase = isB ? g_pb : g_pa;

    const float* Ap = A + (size_t)(bm + row) * DINP + kq;
    const float* Bp = w1 + (size_t)(bnl + row) * 2048 + (isB ? 1024 : 0) + kq;

    ull acc[8][4];
#pragma unroll
    for (int i = 0; i < 8; i++)
#pragma unroll
        for (int j = 0; j < 4; j++) acc[i][j] = 0ull;

    float4 a0v = *(const float4*)(Ap);
    float4 a1v = *(const float4*)(Ap + 4);
    float4 b0v = *(const float4*)(Bp);
    float4 b1v = *(const float4*)(Bp + 4);

    for (int k0 = 0; k0 < DINP; k0 += 16) {
        As[kq + 0][row] = a0v.x; As[kq + 1][row] = a0v.y;
        As[kq + 2][row] = a0v.z; As[kq + 3][row] = a0v.w;
        As[kq + 4][row] = a1v.x; As[kq + 5][row] = a1v.y;
        As[kq + 6][row] = a1v.z; As[kq + 7][row] = a1v.w;
        Bs[kq + 0][row] = b0v.x; Bs[kq + 1][row] = b0v.y;
        Bs[kq + 2][row] = b0v.z; Bs[kq + 3][row] = b0v.w;
        Bs[kq + 4][row] = b1v.x; Bs[kq + 5][row] = b1v.y;
        Bs[kq + 6][row] = b1v.z; Bs[kq + 7][row] = b1v.w;
        __syncthreads();

        if (k0 + 16 < DINP) {
            a0v = *(const float4*)(Ap + k0 + 16);
            a1v = *(const float4*)(Ap + k0 + 20);
            b0v = *(const float4*)(Bp + k0 + 16);
            b1v = *(const float4*)(Bp + k0 + 20);
        }

#pragma unroll
        for (int k = 0; k < 16; k++) {
            float4 am0 = *(const float4*)&As[k][m0];
            float4 am1 = *(const float4*)&As[k][m0 + 64];
            ulonglong2 bb0 = *(const ulonglong2*)&Bs[k][n0];
            ulonglong2 bb1 = *(const ulonglong2*)&Bs[k][n0 + 64];
            ull ad[8];
            ad[0] = pk2(am0.x); ad[1] = pk2(am0.y); ad[2] = pk2(am0.z); ad[3] = pk2(am0.w);
            ad[4] = pk2(am1.x); ad[5] = pk2(am1.y); ad[6] = pk2(am1.z); ad[7] = pk2(am1.w);
#pragma unroll
            for (int i = 0; i < 8; i++) {
                fma2(acc[i][0], ad[i], bb0.x);
                fma2(acc[i][1], ad[i], bb0.y);
                fma2(acc[i][2], ad[i], bb1.x);
                fma2(acc[i][3], ad[i], bb1.y);
            }
        }
        __syncthreads();
    }

    float bz[8];
#pragma unroll
    for (int jj = 0; jj < 8; jj++) {
        int n = bnl + n0 + ((jj < 4) ? jj : 60 + jj);
        bz[jj] = isB ? b1[n] : 0.0f;
    }
#pragma unroll
    for (int i = 0; i < 8; i++) {
        int m = bm + m0 + ((i < 4) ? i : 60 + i);
        float* Cr = Cbase + (size_t)m * HID + bnl + n0;
        Cr[0]  = lo2(acc[i][0]) + bz[0];
        Cr[1]  = hi2(acc[i][0]) + bz[1];
        Cr[2]  = lo2(acc[i][1]) + bz[2];
        Cr[3]  = hi2(acc[i][1]) + bz[3];
        Cr[64] = lo2(acc[i][2]) + bz[4];
        Cr[65] = hi2(acc[i][2]) + bz[5];
        Cr[66] = lo2(acc[i][3]) + bz[6];
        Cr[67] = hi2(acc[i][3]) + bz[7];
    }
}

// ---------------- persistent bidirectional LSTM scan (R14 protocol, 512 threads) ----------------
// 128 blocks: [0,64) fwd, [64,128) bwd; each owns 8 hidden units (32 gate rows).
// Parity-tagged h (R14): 2-bit step tag in low mantissa bits; data IS the flag.
// 512 threads: 16 k-chunks of 32 -> matvec dependency chain halved.
// Warp-local gather preserved: warp w owns producers [4w,4w+4) = hbuf [32w,32w+32)
// = its own matvec chunk kc=w.
__global__ __launch_bounds__(512, 1) void lstm_kernel(
    const float* __restrict__ pre,     // [TOK][4096], bias folded
    const float* __restrict__ whh,     // [2][2048][512] this layer
    const int* __restrict__ length,
    float* __restrict__ xout,          // [TOK][1024]
    int base)                          // l*SLEN
{
    __shared__ float4 hbuf[512];       // h[k][4 batch]
    __shared__ ull    red2[1024];      // matvec partials (packed batch pairs)
    __shared__ ull    gsum2[64];       // reduced gates  (packed batch pairs)

    const int tid = threadIdx.x;
    const int d   = blockIdx.x >> 6;
    const int blk = blockIdx.x & 63;
    const int u0  = blk * 8;
    const int r   = tid & 31;          // local gate-row (gate = r>>3, j = r&7)
    const int kc  = tid >> 5;          // k-chunk 0..15 (= warp id)

    // register-resident scalar W_hh slice (32 regs)
    float wreg[32];
    {
        const float* wp = whh + (size_t)d * GHID * HID
                        + (size_t)((r >> 3) * HID + u0 + (r & 7)) * HID + kc * 32;
#pragma unroll
        for (int kk = 0; kk < 32; kk++) wreg[kk] = wp[kk];
    }

    const bool is_act = (tid >= 480);  // warp 15
    const int lane = tid & 31;
    const int j7 = lane & 7, b7 = lane >> 3;
    float creg = 0.0f, hreg = 0.0f;
    const int len_b = is_act ? length[b7] : 0;

    for (int s = 0; s < SLEN; s++) {
        const int t = d ? (SLEN - 1 - s) : s;

        // act warp: prefetch pre-activations for owned gates (independent of h)
        float pi = 0.f, pf = 0.f, pg = 0.f, po = 0.f;
        if (is_act) {
            const float* pp = pre + (size_t)(b7 * SLEN + t) * NPRE + d * GHID + u0 + j7;
            pi = pp[0]; pf = pp[512]; pg = pp[1024]; po = pp[1536];
        }

        // warp-local poll+gather: thread tid polls/reads 1 uint4 of producer (tid>>3).
        // Tag match on all 4 words. Data is the flag.
        if (s == 0) {
            hbuf[tid] = make_float4(0.f, 0.f, 0.f, 0.f);
        } else {
            const unsigned want = (unsigned)(base + s) & 3u;
            const uint4* src = ((const uint4*)g_h) + ((s & 1) * 2 + d) * 512 + tid;
            uint4 v0 = ldcg4(src);
            while ((((v0.x ^ want) | (v0.y ^ want) | (v0.z ^ want) | (v0.w ^ want)) & 3u) != 0u) {
                backoff();
                v0 = ldcg4(src);
            }
            ((uint4*)hbuf)[tid] = v0;
        }
        __syncwarp();      // warp-local: this warp's chunk of hbuf is ready

        // matvec: thread (r, kc), 32 k per thread, batch-packed f32x2
        ull a01 = 0ull, a23 = 0ull;
        const ulonglong2* hp = (const ulonglong2*)(hbuf + kc * 32);
#pragma unroll
        for (int kk = 0; kk < 32; kk++) {
            ulonglong2 hv = hp[kk];          // LDS.128 broadcast within warp
            ull wd = pk2(wreg[kk]);          // ALU mov, dual-issues vs fma pipe
            fma2(a01, wd, hv.x);
            fma2(a23, wd, hv.y);
        }
        red2[tid] = a01;
        red2[512 + tid] = a23;
        __syncthreads();   // S2: all partials in red2

        // packed 16-way reduction: 64 threads
        if (tid < 64) {
            const int rr = tid & 31, half = tid >> 5;
            const ull* rp = red2 + half * 512 + rr;
            ull sum = rp[0];
#pragma unroll
            for (int q = 1; q < 16; q++) add2(sum, rp[q * 32]);
            gsum2[half * 32 + rr] = sum;
        }
        __syncthreads();   // S3: gate sums ready; also fences red2 reads vs next write

        // act warp: activation + tagged publish
        if (is_act) {
            const float* gs = (const float*)gsum2;
            const int bb = (b7 >> 1) * 64 + (b7 & 1);
            float gi = pi + gs[bb + (0 * 8 + j7) * 2];
            float gf = pf + gs[bb + (1 * 8 + j7) * 2];
            float gg = pg + gs[bb + (2 * 8 + j7) * 2];
            float go = po + gs[bb + (3 * 8 + j7) * 2];
            float cn = sig_fast(gf) * creg + sig_fast(gi) * tanh_fast(gg);
            float hn = sig_fast(go) * tanh_fast(cn);
            bool m = (t < len_b);
            if (m) { creg = cn; hreg = hn; }
            // publish h into buffer (s+1)&1 with 2-bit step tag in low mantissa bits
            const unsigned tag = (unsigned)(base + s + 1) & 3u;
            unsigned hb = (__float_as_uint(hreg) & ~3u) | tag;
            stcg1u(&g_h[((((s + 1) & 1) * 2 + d) * 512 + u0 + j7) * 4 + b7], hb);
            xout[(size_t)(b7 * SLEN + t) * DINP + d * HID + u0 + j7] = m ? hn : 0.0f;
        }
    }
}

// ---------------- score: out[b,s,t] = b2 + sum_h w2[h]*tanh(pa[b,s,h]+pbb[b,t,h]) ----------------
__global__ __launch_bounds__(256) void score_kernel(
    const float* __restrict__ pa, const float* __restrict__ pb,
    const float* __restrict__ w2, const float* __restrict__ b2,
    float* __restrict__ out)
{
    extern __shared__ float sm[];
    float* paT = sm;                 // [512][17]
    float* pbT = sm + 512 * 17;
    float* w2s = pbT + 512 * 17;     // [512]

    const int tid = threadIdx.x;
    const int btt = blockIdx.x, bss = blockIdx.y, b = blockIdx.z;

    for (int idx = tid; idx < 16 * 512; idx += 256) {
        int row = idx >> 9, h = idx & 511;
        paT[h * 17 + row] = pa[(size_t)(b * SLEN + bss * 16 + row) * HID + h];
        pbT[h * 17 + row] = pb[(size_t)(b * SLEN + btt * 16 + row) * HID + h];
    }
    for (int idx = tid; idx < 512; idx += 256) w2s[idx] = w2[idx];
    __syncthreads();

    const int si = tid & 15, ti = tid >> 4;
    float acc = 0.0f;
#pragma unroll 8
    for (int h = 0; h < 512; h++) {
        float x = paT[h * 17 + si] + pbT[h * 17 + ti];
        acc = fmaf(w2s[h], tanh_fast(x), acc);
    }
    out[(size_t)(b * SLEN + bss * 16 + si) * SLEN + btt * 16 + ti] = acc + b2[0];
}

// ---------------- launch ----------------
extern "C" void kernel_launch(void* const* d_in, const int* in_sizes, int n_in,
                              void* d_out, int out_size)
{
    const int*   sent   = (const int*)d_in[0];
    const int*   pos    = (const int*)d_in[1];
    const int*   length = (const int*)d_in[2];
    const float* emb    = (const float*)d_in[3];
    const float* w_ih   = (const float*)d_in[4];
    const float* w_hh   = (const float*)d_in[5];
    const float* b_ih   = (const float*)d_in[6];
    const float* b_hh   = (const float*)d_in[7];
    const float* w1     = (const float*)d_in[8];
    const float* b1     = (const float*)d_in[9];
    const float* w2     = (const float*)d_in[10];
    const float* b2     = (const float*)d_in[11];
    float* out = (float*)d_out;

    const int SCORE_SMEM = 2 * 512 * 17 * 4 + 512 * 4;
    cudaFuncSetAttribute(score_kernel, cudaFuncAttributeMaxDynamicSharedMemorySize, SCORE_SMEM);

    float *xA, *xB, *prep, *pap, *pbp;
    cudaGetSymbolAddress((void**)&xA,   g_xA);
    cudaGetSymbolAddress((void**)&xB,   g_xB);
    cudaGetSymbolAddress((void**)&prep, g_pre);
    cudaGetSymbolAddress((void**)&pap,  g_pa);
    cudaGetSymbolAddress((void**)&pbp,  g_pb);

    embed_kernel<<<1024, 256>>>(sent, pos, emb);

    for (int l = 0; l < 2; l++) {
        const float* Ain = l ? xB : xA;
        float* Xout      = l ? xA : xB;
        gemm_kernel<<<dim3(NPRE / 128, TOK / 128), 256>>>(
            Ain, w_ih + (size_t)l * NPRE * DINP, prep,
            NPRE, DINP, DINP, b_ih + l * NPRE, b_hh + l * NPRE);
        lstm_kernel<<<NBLK_TOT, 512>>>(
            prep, w_hh + (size_t)l * 2 * GHID * HID, length, Xout, l * SLEN);
    }

    // merged pa/pb GEMM: 64 blocks, one launch
    gemm_attn_kernel<<<dim3(1024 / 128, TOK / 128), 256>>>(xA, w1, b1);

    score_kernel<<<dim3(16, 16, 4), 256, SCORE_SMEM>>>(pap, pbp, w2, b2, out);
}

// round 16
// speedup vs baseline: 2.1461x; 1.0286x over previous
#include <cuda_runtime.h>
#include <math.h>
#include <stdint.h>

#define TOK   1024   // B*S
#define SLEN  256
#define BATCH 4
#define HID   512
#define DINP  1024
#define GHID  2048
#define NPRE  4096   // 2 dirs * 4H

#define NBLK     64      // blocks per direction in lstm kernel
#define NBLK_TOT 128

typedef unsigned long long ull;

// ---------------- device scratch (static, no allocation) ----------------
__device__ float g_xA[TOK * DINP];
__device__ float g_xB[TOK * DINP];
__device__ float g_pre[TOK * NPRE];
__device__ float g_pa[TOK * HID];
__device__ float g_pb[TOK * HID];
__device__ float g_h[2 * 2 * HID * 4];   // [buf][dir][k][batch], zero-init at load

// ---------------- helpers ----------------
__device__ __forceinline__ float tanh_fast(float x) {
    float y;
    asm("tanh.approx.f32 %0, %1;" : "=f"(y) : "f"(x));
    return y;
}
__device__ __forceinline__ float sig_fast(float x) {
    return 0.5f * tanh_fast(0.5f * x) + 0.5f;
}
__device__ __forceinline__ ull pk2(float x) {
    ull d; asm("mov.b64 %0, {%1, %1};" : "=l"(d) : "f"(x)); return d;
}
__device__ __forceinline__ void fma2(ull& acc, ull a, ull b) {
    asm("fma.rn.f32x2 %0, %1, %2, %0;" : "+l"(acc) : "l"(a), "l"(b));
}
__device__ __forceinline__ void add2(ull& acc, ull a) {
    asm("add.rn.f32x2 %0, %0, %1;" : "+l"(acc) : "l"(a));
}
__device__ __forceinline__ float lo2(ull v) { return __uint_as_float((unsigned)v); }
__device__ __forceinline__ float hi2(ull v) { return __uint_as_float((unsigned)(v >> 32)); }
__device__ __forceinline__ uint4 ldcg4(const uint4* p) {
    uint4 v;
    asm volatile("ld.global.cg.v4.u32 {%0,%1,%2,%3}, [%4];"
        : "=r"(v.x), "=r"(v.y), "=r"(v.z), "=r"(v.w) : "l"(p) : "memory");
    return v;
}
__device__ __forceinline__ void stcg1u(float* p, unsigned v) {
    asm volatile("st.global.cg.b32 [%0], %1;" :: "l"(p), "r"(v) : "memory");
}
__device__ __forceinline__ void backoff() {
    asm volatile("nanosleep.u32 64;");
}

// ---------------- embedding gather + concat ----------------
__global__ __launch_bounds__(256) void embed_kernel(
    const int* __restrict__ sent, const int* __restrict__ pos,
    const float* __restrict__ emb)
{
    int gid = blockIdx.x * 256 + threadIdx.x;
    int token = gid >> 8;
    int q = gid & 255;
    const float4* src;
    if (q < 128) src = (const float4*)(emb + (size_t)sent[token] * HID) + q;
    else         src = (const float4*)(emb + (size_t)pos[token]  * HID) + (q - 128);
    ((float4*)g_xA)[gid] = *src;
}

// ---------------- fp32x2 SIMT GEMM, double-buffered: C = A * B^T + bias(n) ----------------
// One __syncthreads per 16-k tile: prefetch regs -> compute buf[cur] ->
// store into buf[cur^1] -> sync. WAR safe: buf[cur^1]'s prior readers all
// crossed the previous iteration's sync.
__global__ __launch_bounds__(256, 2) void gemm_kernel(
    const float* __restrict__ A, const float* __restrict__ B,
    float* __restrict__ C, int N, int K, int ldb,
    const float* __restrict__ bias1, const float* __restrict__ bias2)
{
    __shared__ float As[2][16][128];
    __shared__ float Bs[2][16][128];
    const int tid = threadIdx.x;
    const int bm = blockIdx.y << 7, bn = blockIdx.x << 7;
    const int row = tid >> 1;
    const int kq  = (tid & 1) << 3;
    const int tx = tid & 15, ty = tid >> 4;
    const int n0 = tx << 2, m0 = ty << 2;

    const float* Ap = A + (size_t)(bm + row) * K + kq;
    const float* Bp = B + (size_t)(bn + row) * ldb + kq;

    ull acc[8][4];
#pragma unroll
    for (int i = 0; i < 8; i++)
#pragma unroll
        for (int j = 0; j < 4; j++) acc[i][j] = 0ull;

    float4 a0v = *(const float4*)(Ap);
    float4 a1v = *(const float4*)(Ap + 4);
    float4 b0v = *(const float4*)(Bp);
    float4 b1v = *(const float4*)(Bp + 4);

    // stage tile 0 into buffer 0
    As[0][kq + 0][row] = a0v.x; As[0][kq + 1][row] = a0v.y;
    As[0][kq + 2][row] = a0v.z; As[0][kq + 3][row] = a0v.w;
    As[0][kq + 4][row] = a1v.x; As[0][kq + 5][row] = a1v.y;
    As[0][kq + 6][row] = a1v.z; As[0][kq + 7][row] = a1v.w;
    Bs[0][kq + 0][row] = b0v.x; Bs[0][kq + 1][row] = b0v.y;
    Bs[0][kq + 2][row] = b0v.z; Bs[0][kq + 3][row] = b0v.w;
    Bs[0][kq + 4][row] = b1v.x; Bs[0][kq + 5][row] = b1v.y;
    Bs[0][kq + 6][row] = b1v.z; Bs[0][kq + 7][row] = b1v.w;
    __syncthreads();

    const int ntiles = K >> 4;
    for (int t = 0; t < ntiles; t++) {
        const int cur = t & 1, nxt = cur ^ 1;
        const bool more = (t + 1 < ntiles);
        if (more) {
            const int k0 = (t + 1) << 4;
            a0v = *(const float4*)(Ap + k0);
            a1v = *(const float4*)(Ap + k0 + 4);
            b0v = *(const float4*)(Bp + k0);
            b1v = *(const float4*)(Bp + k0 + 4);
        }

#pragma unroll
        for (int k = 0; k < 16; k++) {
            float4 am0 = *(const float4*)&As[cur][k][m0];
            float4 am1 = *(const float4*)&As[cur][k][m0 + 64];
            ulonglong2 bb0 = *(const ulonglong2*)&Bs[cur][k][n0];
            ulonglong2 bb1 = *(const ulonglong2*)&Bs[cur][k][n0 + 64];
            ull ad[8];
            ad[0] = pk2(am0.x); ad[1] = pk2(am0.y); ad[2] = pk2(am0.z); ad[3] = pk2(am0.w);
            ad[4] = pk2(am1.x); ad[5] = pk2(am1.y); ad[6] = pk2(am1.z); ad[7] = pk2(am1.w);
#pragma unroll
            for (int i = 0; i < 8; i++) {
                fma2(acc[i][0], ad[i], bb0.x);
                fma2(acc[i][1], ad[i], bb0.y);
                fma2(acc[i][2], ad[i], bb1.x);
                fma2(acc[i][3], ad[i], bb1.y);
            }
        }

        if (more) {
            As[nxt][kq + 0][row] = a0v.x; As[nxt][kq + 1][row] = a0v.y;
            As[nxt][kq + 2][row] = a0v.z; As[nxt][kq + 3][row] = a0v.w;
            As[nxt][kq + 4][row] = a1v.x; As[nxt][kq + 5][row] = a1v.y;
            As[nxt][kq + 6][row] = a1v.z; As[nxt][kq + 7][row] = a1v.w;
            Bs[nxt][kq + 0][row] = b0v.x; Bs[nxt][kq + 1][row] = b0v.y;
            Bs[nxt][kq + 2][row] = b0v.z; Bs[nxt][kq + 3][row] = b0v.w;
            Bs[nxt][kq + 4][row] = b1v.x; Bs[nxt][kq + 5][row] = b1v.y;
            Bs[nxt][kq + 6][row] = b1v.z; Bs[nxt][kq + 7][row] = b1v.w;
            __syncthreads();
        }
    }

    float bz[8];
#pragma unroll
    for (int jj = 0; jj < 8; jj++) {
        int n = bn + n0 + ((jj < 4) ? jj : 60 + jj);
        float bb = 0.0f;
        if (bias1) bb += bias1[n];
        if (bias2) bb += bias2[n];
        bz[jj] = bb;
    }
#pragma unroll
    for (int i = 0; i < 8; i++) {
        int m = bm + m0 + ((i < 4) ? i : 60 + i);
        float* Cr = C + (size_t)m * N + bn + n0;
        Cr[0]  = lo2(acc[i][0]) + bz[0];
        Cr[1]  = hi2(acc[i][0]) + bz[1];
        Cr[2]  = lo2(acc[i][1]) + bz[2];
        Cr[3]  = hi2(acc[i][1]) + bz[3];
        Cr[64] = lo2(acc[i][2]) + bz[4];
        Cr[65] = hi2(acc[i][2]) + bz[5];
        Cr[66] = lo2(acc[i][3]) + bz[6];
        Cr[67] = hi2(acc[i][3]) + bz[7];
    }
}

// ---------------- merged attention GEMM, double-buffered ----------------
// pa = X@wa^T (n<512) ; pb = X@wb^T + b1 (n>=512). 512%128==0 -> uniform tiles.
__global__ __launch_bounds__(256, 2) void gemm_attn_kernel(
    const float* __restrict__ A, const float* __restrict__ w1,
    const float* __restrict__ b1)
{
    __shared__ float As[2][16][128];
    __shared__ float Bs[2][16][128];
    const int tid = threadIdx.x;
    const int bm = blockIdx.y << 7, bn = blockIdx.x << 7;
    const int row = tid >> 1;
    const int kq  = (tid & 1) << 3;
    const int tx = tid & 15, ty = tid >> 4;
    const int n0 = tx << 2, m0 = ty << 2;

    const bool isB = (bn >= 512);
    const int bnl = isB ? (bn - 512) : bn;
    float* Cbase = isB ? g_pb : g_pa;

    const float* Ap = A + (size_t)(bm + row) * DINP + kq;
    const float* Bp = w1 + (size_t)(bnl + row) * 2048 + (isB ? 1024 : 0) + kq;

    ull acc[8][4];
#pragma unroll
    for (int i = 0; i < 8; i++)
#pragma unroll
        for (int j = 0; j < 4; j++) acc[i][j] = 0ull;

    float4 a0v = *(const float4*)(Ap);
    float4 a1v = *(const float4*)(Ap + 4);
    float4 b0v = *(const float4*)(Bp);
    float4 b1v = *(const float4*)(Bp + 4);

    As[0][kq + 0][row] = a0v.x; As[0][kq + 1][row] = a0v.y;
    As[0][kq + 2][row] = a0v.z; As[0][kq + 3][row] = a0v.w;
    As[0][kq + 4][row] = a1v.x; As[0][kq + 5][row] = a1v.y;
    As[0][kq + 6][row] = a1v.z; As[0][kq + 7][row] = a1v.w;
    Bs[0][kq + 0][row] = b0v.x; Bs[0][kq + 1][row] = b0v.y;
    Bs[0][kq + 2][row] = b0v.z; Bs[0][kq + 3][row] = b0v.w;
    Bs[0][kq + 4][row] = b1v.x; Bs[0][kq + 5][row] = b1v.y;
    Bs[0][kq + 6][row] = b1v.z; Bs[0][kq + 7][row] = b1v.w;
    __syncthreads();

    const int ntiles = DINP >> 4;
    for (int t = 0; t < ntiles; t++) {
        const int cur = t & 1, nxt = cur ^ 1;
        const bool more = (t + 1 < ntiles);
        if (more) {
            const int k0 = (t + 1) << 4;
            a0v = *(const float4*)(Ap + k0);
            a1v = *(const float4*)(Ap + k0 + 4);
            b0v = *(const float4*)(Bp + k0);
            b1v = *(const float4*)(Bp + k0 + 4);
        }

#pragma unroll
        for (int k = 0; k < 16; k++) {
            float4 am0 = *(const float4*)&As[cur][k][m0];
            float4 am1 = *(const float4*)&As[cur][k][m0 + 64];
            ulonglong2 bb0 = *(const ulonglong2*)&Bs[cur][k][n0];
            ulonglong2 bb1 = *(const ulonglong2*)&Bs[cur][k][n0 + 64];
            ull ad[8];
            ad[0] = pk2(am0.x); ad[1] = pk2(am0.y); ad[2] = pk2(am0.z); ad[3] = pk2(am0.w);
            ad[4] = pk2(am1.x); ad[5] = pk2(am1.y); ad[6] = pk2(am1.z); ad[7] = pk2(am1.w);
#pragma unroll
            for (int i = 0; i < 8; i++) {
                fma2(acc[i][0], ad[i], bb0.x);
                fma2(acc[i][1], ad[i], bb0.y);
                fma2(acc[i][2], ad[i], bb1.x);
                fma2(acc[i][3], ad[i], bb1.y);
            }
        }

        if (more) {
            As[nxt][kq + 0][row] = a0v.x; As[nxt][kq + 1][row] = a0v.y;
            As[nxt][kq + 2][row] = a0v.z; As[nxt][kq + 3][row] = a0v.w;
            As[nxt][kq + 4][row] = a1v.x; As[nxt][kq + 5][row] = a1v.y;
            As[nxt][kq + 6][row] = a1v.z; As[nxt][kq + 7][row] = a1v.w;
            Bs[nxt][kq + 0][row] = b0v.x; Bs[nxt][kq + 1][row] = b0v.y;
            Bs[nxt][kq + 2][row] = b0v.z; Bs[nxt][kq + 3][row] = b0v.w;
            Bs[nxt][kq + 4][row] = b1v.x; Bs[nxt][kq + 5][row] = b1v.y;
            Bs[nxt][kq + 6][row] = b1v.z; Bs[nxt][kq + 7][row] = b1v.w;
            __syncthreads();
        }
    }

    float bz[8];
#pragma unroll
    for (int jj = 0; jj < 8; jj++) {
        int n = bnl + n0 + ((jj < 4) ? jj : 60 + jj);
        bz[jj] = isB ? b1[n] : 0.0f;
    }
#pragma unroll
    for (int i = 0; i < 8; i++) {
        int m = bm + m0 + ((i < 4) ? i : 60 + i);
        float* Cr = Cbase + (size_t)m * HID + bnl + n0;
        Cr[0]  = lo2(acc[i][0]) + bz[0];
        Cr[1]  = hi2(acc[i][0]) + bz[1];
        Cr[2]  = lo2(acc[i][1]) + bz[2];
        Cr[3]  = hi2(acc[i][1]) + bz[3];
        Cr[64] = lo2(acc[i][2]) + bz[4];
        Cr[65] = hi2(acc[i][2]) + bz[5];
        Cr[66] = lo2(acc[i][3]) + bz[6];
        Cr[67] = hi2(acc[i][3]) + bz[7];
    }
}

// ---------------- persistent bidirectional LSTM scan (R15 winner, unchanged) ----------------
__global__ __launch_bounds__(512, 1) void lstm_kernel(
    const float* __restrict__ pre,     // [TOK][4096], bias folded
    const float* __restrict__ whh,     // [2][2048][512] this layer
    const int* __restrict__ length,
    float* __restrict__ xout,          // [TOK][1024]
    int base)                          // l*SLEN
{
    __shared__ float4 hbuf[512];       // h[k][4 batch]
    __shared__ ull    red2[1024];      // matvec partials (packed batch pairs)
    __shared__ ull    gsum2[64];       // reduced gates  (packed batch pairs)

    const int tid = threadIdx.x;
    const int d   = blockIdx.x >> 6;
    const int blk = blockIdx.x & 63;
    const int u0  = blk * 8;
    const int r   = tid & 31;          // local gate-row (gate = r>>3, j = r&7)
    const int kc  = tid >> 5;          // k-chunk 0..15 (= warp id)

    // register-resident scalar W_hh slice (32 regs)
    float wreg[32];
    {
        const float* wp = whh + (size_t)d * GHID * HID
                        + (size_t)((r >> 3) * HID + u0 + (r & 7)) * HID + kc * 32;
#pragma unroll
        for (int kk = 0; kk < 32; kk++) wreg[kk] = wp[kk];
    }

    const bool is_act = (tid >= 480);  // warp 15
    const int lane = tid & 31;
    const int j7 = lane & 7, b7 = lane >> 3;
    float creg = 0.0f, hreg = 0.0f;
    const int len_b = is_act ? length[b7] : 0;

    for (int s = 0; s < SLEN; s++) {
        const int t = d ? (SLEN - 1 - s) : s;

        // act warp: prefetch pre-activations for owned gates (independent of h)
        float pi = 0.f, pf = 0.f, pg = 0.f, po = 0.f;
        if (is_act) {
            const float* pp = pre + (size_t)(b7 * SLEN + t) * NPRE + d * GHID + u0 + j7;
            pi = pp[0]; pf = pp[512]; pg = pp[1024]; po = pp[1536];
        }

        // warp-local poll+gather: thread tid polls/reads 1 uint4 of producer (tid>>3).
        // Tag match on all 4 words. Data is the flag.
        if (s == 0) {
            hbuf[tid] = make_float4(0.f, 0.f, 0.f, 0.f);
        } else {
            const unsigned want = (unsigned)(base + s) & 3u;
            const uint4* src = ((const uint4*)g_h) + ((s & 1) * 2 + d) * 512 + tid;
            uint4 v0 = ldcg4(src);
            while ((((v0.x ^ want) | (v0.y ^ want) | (v0.z ^ want) | (v0.w ^ want)) & 3u) != 0u) {
                backoff();
                v0 = ldcg4(src);
            }
            ((uint4*)hbuf)[tid] = v0;
        }
        __syncwarp();      // warp-local: this warp's chunk of hbuf is ready

        // matvec: thread (r, kc), 32 k per thread, batch-packed f32x2
        ull a01 = 0ull, a23 = 0ull;
        const ulonglong2* hp = (const ulonglong2*)(hbuf + kc * 32);
#pragma unroll
        for (int kk = 0; kk < 32; kk++) {
            ulonglong2 hv = hp[kk];          // LDS.128 broadcast within warp
            ull wd = pk2(wreg[kk]);          // ALU mov, dual-issues vs fma pipe
            fma2(a01, wd, hv.x);
            fma2(a23, wd, hv.y);
        }
        red2[tid] = a01;
        red2[512 + tid] = a23;
        __syncthreads();   // S2: all partials in red2

        // packed 16-way reduction: 64 threads
        if (tid < 64) {
            const int rr = tid & 31, half = tid >> 5;
            const ull* rp = red2 + half * 512 + rr;
            ull sum = rp[0];
#pragma unroll
            for (int q = 1; q < 16; q++) add2(sum, rp[q * 32]);
            gsum2[half * 32 + rr] = sum;
        }
        __syncthreads();   // S3: gate sums ready; also fences red2 reads vs next write

        // act warp: activation + tagged publish
        if (is_act) {
            const float* gs = (const float*)gsum2;
            const int bb = (b7 >> 1) * 64 + (b7 & 1);
            float gi = pi + gs[bb + (0 * 8 + j7) * 2];
            float gf = pf + gs[bb + (1 * 8 + j7) * 2];
            float gg = pg + gs[bb + (2 * 8 + j7) * 2];
            float go = po + gs[bb + (3 * 8 + j7) * 2];
            float cn = sig_fast(gf) * creg + sig_fast(gi) * tanh_fast(gg);
            float hn = sig_fast(go) * tanh_fast(cn);
            bool m = (t < len_b);
            if (m) { creg = cn; hreg = hn; }
            // publish h into buffer (s+1)&1 with 2-bit step tag in low mantissa bits
            const unsigned tag = (unsigned)(base + s + 1) & 3u;
            unsigned hb = (__float_as_uint(hreg) & ~3u) | tag;
            stcg1u(&g_h[((((s + 1) & 1) * 2 + d) * 512 + u0 + j7) * 4 + b7], hb);
            xout[(size_t)(b7 * SLEN + t) * DINP + d * HID + u0 + j7] = m ? hn : 0.0f;
        }
    }
}

// ---------------- score: out[b,s,t] = b2 + sum_h w2[h]*tanh(pa[b,s,h]+pbb[b,t,h]) ----------------
__global__ __launch_bounds__(256) void score_kernel(
    const float* __restrict__ pa, const float* __restrict__ pb,
    const float* __restrict__ w2, const float* __restrict__ b2,
    float* __restrict__ out)
{
    extern __shared__ float sm[];
    float* paT = sm;                 // [512][17]
    float* pbT = sm + 512 * 17;
    float* w2s = pbT + 512 * 17;     // [512]

    const int tid = threadIdx.x;
    const int btt = blockIdx.x, bss = blockIdx.y, b = blockIdx.z;

    for (int idx = tid; idx < 16 * 512; idx += 256) {
        int row = idx >> 9, h = idx & 511;
        paT[h * 17 + row] = pa[(size_t)(b * SLEN + bss * 16 + row) * HID + h];
        pbT[h * 17 + row] = pb[(size_t)(b * SLEN + btt * 16 + row) * HID + h];
    }
    for (int idx = tid; idx < 512; idx += 256) w2s[idx] = w2[idx];
    __syncthreads();

    const int si = tid & 15, ti = tid >> 4;
    float acc = 0.0f;
#pragma unroll 8
    for (int h = 0; h < 512; h++) {
        float x = paT[h * 17 + si] + pbT[h * 17 + ti];
        acc = fmaf(w2s[h], tanh_fast(x), acc);
    }
    out[(size_t)(b * SLEN + bss * 16 + si) * SLEN + btt * 16 + ti] = acc + b2[0];
}

// ---------------- launch ----------------
extern "C" void kernel_launch(void* const* d_in, const int* in_sizes, int n_in,
                              void* d_out, int out_size)
{
    const int*   sent   = (const int*)d_in[0];
    const int*   pos    = (const int*)d_in[1];
    const int*   length = (const int*)d_in[2];
    const float* emb    = (const float*)d_in[3];
    const float* w_ih   = (const float*)d_in[4];
    const float* w_hh   = (const float*)d_in[5];
    const float* b_ih   = (const float*)d_in[6];
    const float* b_hh   = (const float*)d_in[7];
    const float* w1     = (const float*)d_in[8];
    const float* b1     = (const float*)d_in[9];
    const float* w2     = (const float*)d_in[10];
    const float* b2     = (const float*)d_in[11];
    float* out = (float*)d_out;

    const int SCORE_SMEM = 2 * 512 * 17 * 4 + 512 * 4;
    cudaFuncSetAttribute(score_kernel, cudaFuncAttributeMaxDynamicSharedMemorySize, SCORE_SMEM);

    float *xA, *xB, *prep, *pap, *pbp;
    cudaGetSymbolAddress((void**)&xA,   g_xA);
    cudaGetSymbolAddress((void**)&xB,   g_xB);
    cudaGetSymbolAddress((void**)&prep, g_pre);
    cudaGetSymbolAddress((void**)&pap,  g_pa);
    cudaGetSymbolAddress((void**)&pbp,  g_pb);

    embed_kernel<<<1024, 256>>>(sent, pos, emb);

    for (int l = 0; l < 2; l++) {
        const float* Ain = l ? xB : xA;
        float* Xout      = l ? xA : xB;
        gemm_kernel<<<dim3(NPRE / 128, TOK / 128), 256>>>(
            Ain, w_ih + (size_t)l * NPRE * DINP, prep,
            NPRE, DINP, DINP, b_ih + l * NPRE, b_hh + l * NPRE);
        lstm_kernel<<<NBLK_TOT, 512>>>(
            prep, w_hh + (size_t)l * 2 * GHID * HID, length, Xout, l * SLEN);
    }

    // merged pa/pb GEMM: 64 blocks, one launch
    gemm_attn_kernel<<<dim3(1024 / 128, TOK / 128), 256>>>(xA, w1, b1);

    score_kernel<<<dim3(16, 16, 4), 256, SCORE_SMEM>>>(pap, pbp, w2, b2, out);
}

// round 17
// speedup vs baseline: 3.0405x; 1.4168x over previous
#include <cuda_runtime.h>
#include <cuda_fp16.h>
#include <math.h>
#include <stdint.h>

#define TOK   1024   // B*S
#define SLEN  256
#define BATCH 4
#define HID   512
#define DINP  1024
#define GHID  2048
#define NPRE  4096   // 2 dirs * 4H

#define NBLK     64
#define NBLK_TOT 128
#define LDA16    40    // padded halfs per smem tile row (80B, 16B-aligned, bank-spread)

typedef unsigned long long ull;

// ---------------- device scratch (static, no allocation) ----------------
__device__ __half g_x16A[TOK * DINP];
__device__ __half g_x16B[TOK * DINP];
__device__ __half g_wih16[2 * NPRE * DINP];   // fp16 w_ih, both layers
__device__ __half g_wa16[HID * DINP];         // w1[:, :1024]
__device__ __half g_wb16[HID * DINP];         // w1[:, 1024:]
__device__ float  g_pre[TOK * NPRE];
__device__ float  g_pa[TOK * HID];
__device__ float  g_pb[TOK * HID];
__device__ float  g_h[2 * 2 * HID * 4];       // [buf][dir][k][batch], zero-init

// ---------------- helpers ----------------
__device__ __forceinline__ float tanh_fast(float x) {
    float y;
    asm("tanh.approx.f32 %0, %1;" : "=f"(y) : "f"(x));
    return y;
}
__device__ __forceinline__ float sig_fast(float x) {
    return 0.5f * tanh_fast(0.5f * x) + 0.5f;
}
__device__ __forceinline__ ull pk2(float x) {
    ull d; asm("mov.b64 %0, {%1, %1};" : "=l"(d) : "f"(x)); return d;
}
__device__ __forceinline__ void fma2(ull& acc, ull a, ull b) {
    asm("fma.rn.f32x2 %0, %1, %2, %0;" : "+l"(acc) : "l"(a), "l"(b));
}
__device__ __forceinline__ void add2(ull& acc, ull a) {
    asm("add.rn.f32x2 %0, %0, %1;" : "+l"(acc) : "l"(a));
}
__device__ __forceinline__ uint4 ldcg4(const uint4* p) {
    uint4 v;
    asm volatile("ld.global.cg.v4.u32 {%0,%1,%2,%3}, [%4];"
        : "=r"(v.x), "=r"(v.y), "=r"(v.z), "=r"(v.w) : "l"(p) : "memory");
    return v;
}
__device__ __forceinline__ void stcg1u(float* p, unsigned v) {
    asm volatile("st.global.cg.b32 [%0], %1;" :: "l"(p), "r"(v) : "memory");
}
__device__ __forceinline__ void backoff() {
    asm volatile("nanosleep.u32 64;");
}
__device__ __forceinline__ void ldsm4(unsigned* r, unsigned addr) {
    asm volatile("ldmatrix.sync.aligned.m8n8.x4.shared.b16 {%0,%1,%2,%3}, [%4];"
        : "=r"(r[0]), "=r"(r[1]), "=r"(r[2]), "=r"(r[3]) : "r"(addr));
}
__device__ __forceinline__ void mma16816(float* c, const unsigned* a, const unsigned* b) {
    asm volatile("mma.sync.aligned.m16n8k16.row.col.f32.f16.f16.f32 "
        "{%0,%1,%2,%3}, {%4,%5,%6,%7}, {%8,%9}, {%0,%1,%2,%3};"
        : "+f"(c[0]), "+f"(c[1]), "+f"(c[2]), "+f"(c[3])
        : "r"(a[0]), "r"(a[1]), "r"(a[2]), "r"(a[3]), "r"(b[0]), "r"(b[1]));
}

// ---------------- fp32 -> fp16 conversions ----------------
__global__ __launch_bounds__(256) void conv_wih_kernel(const float* __restrict__ src) {
    int idx = blockIdx.x * 256 + threadIdx.x;   // over count/4
    float4 v = ((const float4*)src)[idx];
    __half2* d = (__half2*)g_wih16 + 2 * idx;
    d[0] = __floats2half2_rn(v.x, v.y);
    d[1] = __floats2half2_rn(v.z, v.w);
}
__global__ __launch_bounds__(256) void conv_w1_kernel(const float* __restrict__ w1) {
    int idx = blockIdx.x * 256 + threadIdx.x;   // over 512*1024/4
    int row = idx >> 8;          // /256 float4s per row
    int c4  = idx & 255;
    float4 va = ((const float4*)(w1 + (size_t)row * 2048))[c4];
    float4 vb = ((const float4*)(w1 + (size_t)row * 2048 + 1024))[c4];
    __half2* da = (__half2*)g_wa16 + 2 * idx;
    __half2* db = (__half2*)g_wb16 + 2 * idx;
    da[0] = __floats2half2_rn(va.x, va.y);
    da[1] = __floats2half2_rn(va.z, va.w);
    db[0] = __floats2half2_rn(vb.x, vb.y);
    db[1] = __floats2half2_rn(vb.z, vb.w);
}

// ---------------- embedding gather + concat (fp16 out) ----------------
__global__ __launch_bounds__(256) void embed_kernel(
    const int* __restrict__ sent, const int* __restrict__ pos,
    const float* __restrict__ emb)
{
    int gid = blockIdx.x * 256 + threadIdx.x;   // over TOK*256 float4s
    int token = gid >> 8;
    int q = gid & 255;
    const float4* src;
    if (q < 128) src = (const float4*)(emb + (size_t)sent[token] * HID) + q;
    else         src = (const float4*)(emb + (size_t)pos[token]  * HID) + (q - 128);
    float4 v = *src;
    __half2* d = (__half2*)g_x16A + 2 * gid;
    d[0] = __floats2half2_rn(v.x, v.y);
    d[1] = __floats2half2_rn(v.z, v.w);
}

// ---------------- fp16 tensor-core GEMM: C[M=1024][N] = A16 @ B16^T + bias ----------------
// Tiles: block 128x128, BK=32, 8 warps in 2x4 (m x n), warp tile 64x32.
// A16: [1024][1024] row-major; B16: [N][ldb] row-major (= col-major operand).
// smem rows padded to 40 halfs; ldmatrix + mma.m16n8k16, double-buffered.
__global__ __launch_bounds__(256, 2) void gemm16_kernel(
    const __half* __restrict__ A, const __half* __restrict__ B,
    float* __restrict__ C, int N, int ldb,
    const float* __restrict__ bias1, const float* __restrict__ bias2)
{
    __shared__ __half As[2][128 * LDA16];
    __shared__ __half Bs[2][128 * LDA16];

    const int tid = threadIdx.x;
    const int lane = tid & 31;
    const int warp = tid >> 5;
    const int wm = warp >> 2;          // 0..1
    const int wn = warp & 3;           // 0..3
    const int bm = blockIdx.y << 7, bn = blockIdx.x << 7;

    // gmem load mapping: 2 uint4 per thread per operand per tile
    const int r0 = tid >> 2;                   // rows 0..63   (idx = tid)
    const int r1 = (tid + 256) >> 2;           // rows 64..127 (idx = tid+256)
    const int sg = (tid & 3) << 3;             // k-offset in halfs {0,8,16,24}

    const __half* Ap0 = A + (size_t)(bm + r0) * DINP + sg;
    const __half* Ap1 = A + (size_t)(bm + r1) * DINP + sg;
    const __half* Bp0 = B + (size_t)(bn + r0) * ldb + sg;
    const __half* Bp1 = B + (size_t)(bn + r1) * ldb + sg;

    const int so = r0 * LDA16 + sg;            // smem store offsets (halfs)
    const int so1 = r1 * LDA16 + sg;

    float acc[4][4][4];
#pragma unroll
    for (int i = 0; i < 4; i++)
#pragma unroll
        for (int j = 0; j < 4; j++)
#pragma unroll
            for (int q = 0; q < 4; q++) acc[i][j][q] = 0.0f;

    // stage tile 0
    uint4 a0 = *(const uint4*)(Ap0), a1 = *(const uint4*)(Ap1);
    uint4 b0 = *(const uint4*)(Bp0), b1 = *(const uint4*)(Bp1);
    *(uint4*)&As[0][so]  = a0; *(uint4*)&As[0][so1] = a1;
    *(uint4*)&Bs[0][so]  = b0; *(uint4*)&Bs[0][so1] = b1;
    __syncthreads();

    // ldmatrix lane address components (in halfs, within a buffer)
    const int aRow = wm * 64 + (lane & 15);    // + i*16
    const int aCol = (lane >> 4) << 3;         // + k16
    const int bRow = wn * 32 + ((lane >> 4) << 3) + (lane & 7);   // + pair*16
    const int bCol = ((lane >> 3) & 1) << 3;   // + k16

    const unsigned asBase0 = (unsigned)__cvta_generic_to_shared(&As[0][0]);
    const unsigned asBase1 = (unsigned)__cvta_generic_to_shared(&As[1][0]);
    const unsigned bsBase0 = (unsigned)__cvta_generic_to_shared(&Bs[0][0]);
    const unsigned bsBase1 = (unsigned)__cvta_generic_to_shared(&Bs[1][0]);

    const int ntiles = DINP >> 5;   // K=1024, BK=32
    for (int t = 0; t < ntiles; t++) {
        const int cur = t & 1;
        const bool more = (t + 1 < ntiles);
        if (more) {
            const int k0 = (t + 1) << 5;
            a0 = *(const uint4*)(Ap0 + k0); a1 = *(const uint4*)(Ap1 + k0);
            b0 = *(const uint4*)(Bp0 + k0); b1 = *(const uint4*)(Bp1 + k0);
        }

        const unsigned aB = cur ? asBase1 : asBase0;
        const unsigned bB = cur ? bsBase1 : bsBase0;
#pragma unroll
        for (int k16 = 0; k16 < 32; k16 += 16) {
            unsigned afr[4][4], bfr[2][4];
#pragma unroll
            for (int i = 0; i < 4; i++) {
                unsigned ad = aB + (((aRow + i * 16) * LDA16) + aCol + k16) * 2;
                ldsm4(afr[i], ad);
            }
#pragma unroll
            for (int p = 0; p < 2; p++) {
                unsigned bd = bB + (((bRow + p * 16) * LDA16) + bCol + k16) * 2;
                ldsm4(bfr[p], bd);
            }
#pragma unroll
            for (int i = 0; i < 4; i++)
#pragma unroll
                for (int j = 0; j < 4; j++)
                    mma16816(acc[i][j], afr[i], &bfr[j >> 1][(j & 1) << 1]);
        }

        if (more) {
            const int nxt = cur ^ 1;
            __half* An = As[nxt]; __half* Bn = Bs[nxt];
            *(uint4*)&An[so]  = a0; *(uint4*)&An[so1] = a1;
            *(uint4*)&Bn[so]  = b0; *(uint4*)&Bn[so1] = b1;
            __syncthreads();
        }
    }

    // epilogue: c frag mapping row=lane/4, col=(lane&3)*2 (+8 rows for c2/c3)
    const int row4 = lane >> 2;
    const int col2 = (lane & 3) << 1;
#pragma unroll
    for (int j = 0; j < 4; j++) {
        const int ng = bn + wn * 32 + j * 8 + col2;
        float bz0 = 0.0f, bz1 = 0.0f;
        if (bias1) { bz0 += bias1[ng]; bz1 += bias1[ng + 1]; }
        if (bias2) { bz0 += bias2[ng]; bz1 += bias2[ng + 1]; }
#pragma unroll
        for (int i = 0; i < 4; i++) {
            const int mg = bm + wm * 64 + i * 16 + row4;
            float* Cr0 = C + (size_t)mg * N + ng;
            float* Cr1 = C + (size_t)(mg + 8) * N + ng;
            Cr0[0] = acc[i][j][0] + bz0;
            Cr0[1] = acc[i][j][1] + bz1;
            Cr1[0] = acc[i][j][2] + bz0;
            Cr1[1] = acc[i][j][3] + bz1;
        }
    }
}

// ---------------- persistent bidirectional LSTM scan (R15/16 winner, fp16 xout) ----------------
__global__ __launch_bounds__(512, 1) void lstm_kernel(
    const float* __restrict__ pre,     // [TOK][4096], bias folded
    const float* __restrict__ whh,     // [2][2048][512] this layer
    const int* __restrict__ length,
    __half* __restrict__ xout,         // [TOK][1024] fp16
    int base)                          // l*SLEN
{
    __shared__ float4 hbuf[512];       // h[k][4 batch]
    __shared__ ull    red2[1024];      // matvec partials (packed batch pairs)
    __shared__ ull    gsum2[64];       // reduced gates  (packed batch pairs)

    const int tid = threadIdx.x;
    const int d   = blockIdx.x >> 6;
    const int blk = blockIdx.x & 63;
    const int u0  = blk * 8;
    const int r   = tid & 31;          // local gate-row (gate = r>>3, j = r&7)
    const int kc  = tid >> 5;          // k-chunk 0..15 (= warp id)

    float wreg[32];
    {
        const float* wp = whh + (size_t)d * GHID * HID
                        + (size_t)((r >> 3) * HID + u0 + (r & 7)) * HID + kc * 32;
#pragma unroll
        for (int kk = 0; kk < 32; kk++) wreg[kk] = wp[kk];
    }

    const bool is_act = (tid >= 480);  // warp 15
    const int lane = tid & 31;
    const int j7 = lane & 7, b7 = lane >> 3;
    float creg = 0.0f, hreg = 0.0f;
    const int len_b = is_act ? length[b7] : 0;

    for (int s = 0; s < SLEN; s++) {
        const int t = d ? (SLEN - 1 - s) : s;

        float pi = 0.f, pf = 0.f, pg = 0.f, po = 0.f;
        if (is_act) {
            const float* pp = pre + (size_t)(b7 * SLEN + t) * NPRE + d * GHID + u0 + j7;
            pi = pp[0]; pf = pp[512]; pg = pp[1024]; po = pp[1536];
        }

        // warp-local poll+gather with 2-bit parity tags (data IS the flag)
        if (s == 0) {
            hbuf[tid] = make_float4(0.f, 0.f, 0.f, 0.f);
        } else {
            const unsigned want = (unsigned)(base + s) & 3u;
            const uint4* src = ((const uint4*)g_h) + ((s & 1) * 2 + d) * 512 + tid;
            uint4 v0 = ldcg4(src);
            while ((((v0.x ^ want) | (v0.y ^ want) | (v0.z ^ want) | (v0.w ^ want)) & 3u) != 0u) {
                backoff();
                v0 = ldcg4(src);
            }
            ((uint4*)hbuf)[tid] = v0;
        }
        __syncwarp();

        ull a01 = 0ull, a23 = 0ull;
        const ulonglong2* hp = (const ulonglong2*)(hbuf + kc * 32);
#pragma unroll
        for (int kk = 0; kk < 32; kk++) {
            ulonglong2 hv = hp[kk];
            ull wd = pk2(wreg[kk]);
            fma2(a01, wd, hv.x);
            fma2(a23, wd, hv.y);
        }
        red2[tid] = a01;
        red2[512 + tid] = a23;
        __syncthreads();   // S2

        if (tid < 64) {
            const int rr = tid & 31, half = tid >> 5;
            const ull* rp = red2 + half * 512 + rr;
            ull sum = rp[0];
#pragma unroll
            for (int q = 1; q < 16; q++) add2(sum, rp[q * 32]);
            gsum2[half * 32 + rr] = sum;
        }
        __syncthreads();   // S3

        if (is_act) {
            const float* gs = (const float*)gsum2;
            const int bb = (b7 >> 1) * 64 + (b7 & 1);
            float gi = pi + gs[bb + (0 * 8 + j7) * 2];
            float gf = pf + gs[bb + (1 * 8 + j7) * 2];
            float gg = pg + gs[bb + (2 * 8 + j7) * 2];
            float go = po + gs[bb + (3 * 8 + j7) * 2];
            float cn = sig_fast(gf) * creg + sig_fast(gi) * tanh_fast(gg);
            float hn = sig_fast(go) * tanh_fast(cn);
            bool m = (t < len_b);
            if (m) { creg = cn; hreg = hn; }
            const unsigned tag = (unsigned)(base + s + 1) & 3u;
            unsigned hb = (__float_as_uint(hreg) & ~3u) | tag;
            stcg1u(&g_h[((((s + 1) & 1) * 2 + d) * 512 + u0 + j7) * 4 + b7], hb);
            xout[(size_t)(b7 * SLEN + t) * DINP + d * HID + u0 + j7] =
                __float2half(m ? hn : 0.0f);
        }
    }
}

// ---------------- score: out[b,s,t] = b2 + sum_h w2[h]*tanh(pa[b,s,h]+pbb[b,t,h]) ----------------
__global__ __launch_bounds__(256) void score_kernel(
    const float* __restrict__ pa, const float* __restrict__ pb,
    const float* __restrict__ w2, const float* __restrict__ b2,
    float* __restrict__ out)
{
    extern __shared__ float sm[];
    float* paT = sm;                 // [512][17]
    float* pbT = sm + 512 * 17;
    float* w2s = pbT + 512 * 17;     // [512]

    const int tid = threadIdx.x;
    const int btt = blockIdx.x, bss = blockIdx.y, b = blockIdx.z;

    for (int idx = tid; idx < 16 * 512; idx += 256) {
        int row = idx >> 9, h = idx & 511;
        paT[h * 17 + row] = pa[(size_t)(b * SLEN + bss * 16 + row) * HID + h];
        pbT[h * 17 + row] = pb[(size_t)(b * SLEN + btt * 16 + row) * HID + h];
    }
    for (int idx = tid; idx < 512; idx += 256) w2s[idx] = w2[idx];
    __syncthreads();

    const int si = tid & 15, ti = tid >> 4;
    float acc = 0.0f;
#pragma unroll 8
    for (int h = 0; h < 512; h++) {
        float x = paT[h * 17 + si] + pbT[h * 17 + ti];
        acc = fmaf(w2s[h], tanh_fast(x), acc);
    }
    out[(size_t)(b * SLEN + bss * 16 + si) * SLEN + btt * 16 + ti] = acc + b2[0];
}

// ---------------- launch ----------------
extern "C" void kernel_launch(void* const* d_in, const int* in_sizes, int n_in,
                              void* d_out, int out_size)
{
    const int*   sent   = (const int*)d_in[0];
    const int*   pos    = (const int*)d_in[1];
    const int*   length = (const int*)d_in[2];
    const float* emb    = (const float*)d_in[3];
    const float* w_ih   = (const float*)d_in[4];
    const float* w_hh   = (const float*)d_in[5];
    const float* b_ih   = (const float*)d_in[6];
    const float* b_hh   = (const float*)d_in[7];
    const float* w1     = (const float*)d_in[8];
    const float* b1     = (const float*)d_in[9];
    const float* w2     = (const float*)d_in[10];
    const float* b2     = (const float*)d_in[11];
    float* out = (float*)d_out;

    const int SCORE_SMEM = 2 * 512 * 17 * 4 + 512 * 4;
    cudaFuncSetAttribute(score_kernel, cudaFuncAttributeMaxDynamicSharedMemorySize, SCORE_SMEM);

    __half *x16A, *x16B, *wih16, *wa16, *wb16;
    float *prep, *pap, *pbp;
    cudaGetSymbolAddress((void**)&x16A,  g_x16A);
    cudaGetSymbolAddress((void**)&x16B,  g_x16B);
    cudaGetSymbolAddress((void**)&wih16, g_wih16);
    cudaGetSymbolAddress((void**)&wa16,  g_wa16);
    cudaGetSymbolAddress((void**)&wb16,  g_wb16);
    cudaGetSymbolAddress((void**)&prep,  g_pre);
    cudaGetSymbolAddress((void**)&pap,   g_pa);
    cudaGetSymbolAddress((void**)&pbp,   g_pb);

    conv_wih_kernel<<<(2 * NPRE * DINP / 4) / 256, 256>>>(w_ih);
    conv_w1_kernel<<<(HID * DINP / 4) / 256, 256>>>(w1);
    embed_kernel<<<1024, 256>>>(sent, pos, emb);

    for (int l = 0; l < 2; l++) {
        const __half* Ain = l ? x16B : x16A;
        __half* Xout      = l ? x16A : x16B;
        gemm16_kernel<<<dim3(NPRE / 128, TOK / 128), 256>>>(
            Ain, wih16 + (size_t)l * NPRE * DINP, prep,
            NPRE, DINP, b_ih + l * NPRE, b_hh + l * NPRE);
        lstm_kernel<<<NBLK_TOT, 512>>>(
            prep, w_hh + (size_t)l * 2 * GHID * HID, length, Xout, l * SLEN);
    }

    gemm16_kernel<<<dim3(HID / 128, TOK / 128), 256>>>(
        x16A, wa16, pap, HID, DINP, nullptr, nullptr);
    gemm16_kernel<<<dim3(HID / 128, TOK / 128), 256>>>(
        x16A, wb16, pbp, HID, DINP, b1, nullptr);

    score_kernel<<<dim3(16, 16, 4), 256, SCORE_SMEM>>>(pap, pbp, w2, b2, out);
}